// round 11
// baseline (speedup 1.0000x reference)
#include <cuda_runtime.h>
#include <cuda_bf16.h>
#include <mma.h>
#include <math.h>

using namespace nvcuda;
typedef __nv_bfloat16 bf16;

#define NB 8
#define NC 512
#define NC8 64
#define NHW 4096

#define NEG_INF (__int_as_float(0xff800000))

// Scratch (__device__ globals; allocation-free rule)
__device__ bf16  g_pq[NB * NHW * NC8];    //  4.2 MB  [b][hw][c8]
__device__ bf16  g_pk[NB * NHW * NC8];    //  4.2 MB  [b][hw][c8]
__device__ bf16  g_pv[NB * NHW * NC];     // 33.5 MB  [b][hw][c]
__device__ float g_attH[NB * NHW * 64];   //  8.4 MB  eH logits fp32 (compact)
__device__ bf16  g_attb[NB * NHW * 128];  //  8.4 MB  softmaxed bf16
__device__ bf16  g_oH[NB * NHW * NC];     // 33.5 MB  outH, bf16, [b][hw][c]

// Streams/events created at program load (before harness mem checkpoints).
namespace {
struct StreamSet {
  cudaStream_t s1, s2;
  cudaEvent_t e0, ek, ev, ea, eh0, ew0;
  StreamSet() {
    cudaStreamCreateWithFlags(&s1, cudaStreamNonBlocking);
    cudaStreamCreateWithFlags(&s2, cudaStreamNonBlocking);
    cudaEventCreateWithFlags(&e0, cudaEventDisableTiming);
    cudaEventCreateWithFlags(&ek, cudaEventDisableTiming);
    cudaEventCreateWithFlags(&ev, cudaEventDisableTiming);
    cudaEventCreateWithFlags(&ea, cudaEventDisableTiming);
    cudaEventCreateWithFlags(&eh0, cudaEventDisableTiming);
    cudaEventCreateWithFlags(&ew0, cudaEventDisableTiming);
  }
};
StreamSet g_ss;
}  // namespace

// Pack 8 fp32 (two float4) -> uint4 of bf16
static __device__ __forceinline__ uint4 pack8_bf16(const float4& a, const float4& b) {
  __nv_bfloat162 p0 = __floats2bfloat162_rn(a.x, a.y);
  __nv_bfloat162 p1 = __floats2bfloat162_rn(a.z, a.w);
  __nv_bfloat162 p2 = __floats2bfloat162_rn(b.x, b.y);
  __nv_bfloat162 p3 = __floats2bfloat162_rn(b.z, b.w);
  uint4 u;
  u.x = *(unsigned*)&p0;
  u.y = *(unsigned*)&p1;
  u.z = *(unsigned*)&p2;
  u.w = *(unsigned*)&p3;
  return u;
}

// ---------------------------------------------------------------------------
// Projection GEMM (wmma bf16, reg-prefetch pipelined, vectorized smem fill):
//   P[b][n][m] = sum_k W[m][k] * X[b][k][n] + bias[m]   (channels-last out)
// MSWAP: m-tile on blockIdx.x (fastest) so same-X blocks are launch-adjacent.
// ---------------------------------------------------------------------------
template <int BM, int M, int MINB, bool MSWAP>
__global__ __launch_bounds__(256, MINB) void proj_wmma(
    const float* __restrict__ W, const float* __restrict__ bias,
    const float* __restrict__ X, bf16* __restrict__ P) {
  constexpr int BN = 128, BK = 32;
  constexpr int WMW = BM / 32;
  constexpr int WN = BN / (8 / WMW);
  constexpr int FN = WN / 16;
  constexpr int AITER = BM / 64;

  __shared__ __align__(16) char smem[34816];
  bf16(*As)[40] = (bf16(*)[40])smem;
  bf16(*Bs)[136] = (bf16(*)[136])(smem + BM * 40 * 2);
  float(*Cs)[136] = (float(*)[136])smem;

  const int b = blockIdx.z;
  const int n0 = (MSWAP ? blockIdx.y : blockIdx.x) * BN;
  const int m0 = (MSWAP ? blockIdx.x : blockIdx.y) * BM;
  const int tid = threadIdx.x;
  const int wid = tid >> 5;
  const int wm = wid % WMW;
  const int wn = wid / WMW;
  const float* Xb = X + (size_t)b * NC * NHW;

  wmma::fragment<wmma::accumulator, 16, 16, 16, float> acc[2][FN];
#pragma unroll
  for (int i = 0; i < 2; i++)
#pragma unroll
    for (int j = 0; j < FN; j++) wmma::fill_fragment(acc[i][j], 0.0f);

  float4 aR[AITER][2], bR[2][2];

#pragma unroll
  for (int r = 0; r < AITER; r++) {
    int i = tid + r * 256, row = i >> 2, kb = (i & 3) * 8;
    const float* p = W + (size_t)(m0 + row) * NC + kb;
    aR[r][0] = *(const float4*)p;
    aR[r][1] = *(const float4*)(p + 4);
  }
#pragma unroll
  for (int r = 0; r < 2; r++) {
    int i = tid + r * 256, kr = i >> 4, nb = (i & 15) * 8;
    const float* p = Xb + (size_t)kr * NHW + n0 + nb;
    bR[r][0] = *(const float4*)p;
    bR[r][1] = *(const float4*)(p + 4);
  }

  for (int k0 = 0; k0 < NC; k0 += BK) {
    __syncthreads();
#pragma unroll
    for (int r = 0; r < AITER; r++) {
      int i = tid + r * 256, row = i >> 2, kb = (i & 3) * 8;
      *(uint4*)&As[row][kb] = pack8_bf16(aR[r][0], aR[r][1]);
    }
#pragma unroll
    for (int r = 0; r < 2; r++) {
      int i = tid + r * 256, kr = i >> 4, nb = (i & 15) * 8;
      *(uint4*)&Bs[kr][nb] = pack8_bf16(bR[r][0], bR[r][1]);
    }
    __syncthreads();
    if (k0 + BK < NC) {
#pragma unroll
      for (int r = 0; r < AITER; r++) {
        int i = tid + r * 256, row = i >> 2, kb = (i & 3) * 8;
        const float* p = W + (size_t)(m0 + row) * NC + k0 + BK + kb;
        aR[r][0] = *(const float4*)p;
        aR[r][1] = *(const float4*)(p + 4);
      }
#pragma unroll
      for (int r = 0; r < 2; r++) {
        int i = tid + r * 256, kr = i >> 4, nb = (i & 15) * 8;
        const float* p = Xb + (size_t)(k0 + BK + kr) * NHW + n0 + nb;
        bR[r][0] = *(const float4*)p;
        bR[r][1] = *(const float4*)(p + 4);
      }
    }
#pragma unroll
    for (int kk = 0; kk < BK; kk += 16) {
      wmma::fragment<wmma::matrix_a, 16, 16, 16, bf16, wmma::row_major> af[2];
      wmma::load_matrix_sync(af[0], &As[wm * 32][kk], 40);
      wmma::load_matrix_sync(af[1], &As[wm * 32 + 16][kk], 40);
#pragma unroll
      for (int fn = 0; fn < FN; fn++) {
        wmma::fragment<wmma::matrix_b, 16, 16, 16, bf16, wmma::row_major> bfr;
        wmma::load_matrix_sync(bfr, &Bs[kk][wn * WN + fn * 16], 136);
        wmma::mma_sync(acc[0][fn], af[0], bfr, acc[0][fn]);
        wmma::mma_sync(acc[1][fn], af[1], bfr, acc[1][fn]);
      }
    }
  }

#pragma unroll
  for (int half = 0; half < BM / 64; half++) {
    __syncthreads();
    bool mine = (BM == 64) || ((wm >> 1) == half);
    if (mine) {
      int mloc = (BM == 64) ? wm * 32 : (wm & 1) * 32;
#pragma unroll
      for (int fm = 0; fm < 2; fm++)
#pragma unroll
        for (int fn = 0; fn < FN; fn++)
          wmma::store_matrix_sync(&Cs[mloc + fm * 16][wn * WN + fn * 16],
                                  acc[fm][fn], 136, wmma::mem_row_major);
    }
    __syncthreads();
    const int n = tid >> 1, ml = (tid & 1) * 32;
    const int mg = m0 + half * 64 + ml;
    __align__(16) bf16 ov[32];
#pragma unroll
    for (int i = 0; i < 32; i++)
      ov[i] = __float2bfloat16(Cs[ml + i][n] + bias[mg + i]);
    bf16* dst = P + ((size_t)b * NHW + n0 + n) * M + mg;
#pragma unroll
    for (int i = 0; i < 4; i++) *(uint4*)(dst + i * 8) = *(uint4*)(ov + i * 8);
  }
}

// ---------------------------------------------------------------------------
// eH logits (wmma): per (b, w). E[h][k] = sum_c Q[h][c]*K[k][c]; diag -inf.
// ---------------------------------------------------------------------------
__global__ __launch_bounds__(256) void logits_h_wmma() {
  const int w = blockIdx.x, b = blockIdx.y;
  __shared__ __align__(32) bf16 Qs[64][72];
  __shared__ __align__(32) bf16 Ks[64][72];
  __shared__ __align__(32) float Cs[64][68];
  const int tid = threadIdx.x;
  const int r = tid >> 2, cb = (tid & 3) * 16;

  const bf16* qsrc = g_pq + ((size_t)b * NHW + r * 64 + w) * NC8 + cb;
  const bf16* ksrc = g_pk + ((size_t)b * NHW + r * 64 + w) * NC8 + cb;
  *(uint4*)&Qs[r][cb] = *(const uint4*)qsrc;
  *(uint4*)&Qs[r][cb + 8] = *(const uint4*)(qsrc + 8);
  *(uint4*)&Ks[r][cb] = *(const uint4*)ksrc;
  *(uint4*)&Ks[r][cb + 8] = *(const uint4*)(ksrc + 8);
  __syncthreads();

  const int wid = tid >> 5;
  const int wm = wid & 3, wn = wid >> 2;
  wmma::fragment<wmma::accumulator, 16, 16, 16, float> acc[2];
  wmma::fill_fragment(acc[0], 0.0f);
  wmma::fill_fragment(acc[1], 0.0f);
#pragma unroll
  for (int kk = 0; kk < 64; kk += 16) {
    wmma::fragment<wmma::matrix_a, 16, 16, 16, bf16, wmma::row_major> af;
    wmma::load_matrix_sync(af, &Qs[wm * 16][kk], 72);
#pragma unroll
    for (int j = 0; j < 2; j++) {
      wmma::fragment<wmma::matrix_b, 16, 16, 16, bf16, wmma::col_major> bfr;
      wmma::load_matrix_sync(bfr, &Ks[wn * 32 + j * 16][kk], 72);
      wmma::mma_sync(acc[j], af, bfr, acc[j]);
    }
  }
  wmma::store_matrix_sync(&Cs[wm * 16][wn * 32], acc[0], 68, wmma::mem_row_major);
  wmma::store_matrix_sync(&Cs[wm * 16][wn * 32 + 16], acc[1], 68, wmma::mem_row_major);
  __syncthreads();

  const int h = tid >> 2, kb = (tid & 3) * 16;
  float* dst = g_attH + (((size_t)(b * 64 + h) * 64 + w) << 6) + kb;
#pragma unroll
  for (int i = 0; i < 16; i += 4) {
    float4 v;
    v.x = (h == kb + i + 0) ? NEG_INF : Cs[h][kb + i + 0];
    v.y = (h == kb + i + 1) ? NEG_INF : Cs[h][kb + i + 1];
    v.z = (h == kb + i + 2) ? NEG_INF : Cs[h][kb + i + 2];
    v.w = (h == kb + i + 3) ? NEG_INF : Cs[h][kb + i + 3];
    *(float4*)(dst + i) = v;
  }
}

// ---------------------------------------------------------------------------
// eW logits + fused softmax: per (b, h).
// ---------------------------------------------------------------------------
__global__ __launch_bounds__(256) void logits_w_fused() {
  const int h = blockIdx.x, b = blockIdx.y;
  __shared__ __align__(16) char smQK[18432];
  __shared__ __align__(16) float Es[64][68];
  bf16(*Qs)[72] = (bf16(*)[72])smQK;
  bf16(*Ks)[72] = (bf16(*)[72])(smQK + 9216);
  float(*Cs)[68] = (float(*)[68])smQK;  // aliased after MMA
  const int tid = threadIdx.x;
  const int r = tid >> 2, cb = (tid & 3) * 16;

  const bf16* qsrc = g_pq + ((size_t)b * NHW + h * 64 + r) * NC8 + cb;
  const bf16* ksrc = g_pk + ((size_t)b * NHW + h * 64 + r) * NC8 + cb;
  *(uint4*)&Qs[r][cb] = *(const uint4*)qsrc;
  *(uint4*)&Qs[r][cb + 8] = *(const uint4*)(qsrc + 8);
  *(uint4*)&Ks[r][cb] = *(const uint4*)ksrc;
  *(uint4*)&Ks[r][cb + 8] = *(const uint4*)(ksrc + 8);
  const float* esrc = g_attH + (((size_t)(b * 64 + h) * 64 + r) << 6) + cb;
#pragma unroll
  for (int i = 0; i < 16; i += 4)
    *(float4*)&Es[r][cb + i] = *(const float4*)(esrc + i);
  __syncthreads();

  const int wid = tid >> 5;
  const int wm = wid & 3, wn = wid >> 2;
  wmma::fragment<wmma::accumulator, 16, 16, 16, float> acc[2];
  wmma::fill_fragment(acc[0], 0.0f);
  wmma::fill_fragment(acc[1], 0.0f);
#pragma unroll
  for (int kk = 0; kk < 64; kk += 16) {
    wmma::fragment<wmma::matrix_a, 16, 16, 16, bf16, wmma::row_major> af;
    wmma::load_matrix_sync(af, &Qs[wm * 16][kk], 72);
#pragma unroll
    for (int j = 0; j < 2; j++) {
      wmma::fragment<wmma::matrix_b, 16, 16, 16, bf16, wmma::col_major> bfr;
      wmma::load_matrix_sync(bfr, &Ks[wn * 32 + j * 16][kk], 72);
      wmma::mma_sync(acc[j], af, bfr, acc[j]);
    }
  }
  __syncthreads();  // Qs/Ks reads done; safe to alias as Cs
  wmma::store_matrix_sync(&Cs[wm * 16][wn * 32], acc[0], 68, wmma::mem_row_major);
  wmma::store_matrix_sync(&Cs[wm * 16][wn * 32 + 16], acc[1], 68, wmma::mem_row_major);
  __syncthreads();

  const int lane = tid & 31;
  for (int rr = wid; rr < 64; rr += 8) {
    float4 v;
    if (lane < 16)
      v = *(const float4*)&Es[rr][lane * 4];
    else
      v = *(const float4*)&Cs[rr][(lane - 16) * 4];
    float m = fmaxf(fmaxf(v.x, v.y), fmaxf(v.z, v.w));
#pragma unroll
    for (int o = 16; o; o >>= 1) m = fmaxf(m, __shfl_xor_sync(0xffffffffu, m, o));
    v.x = __expf(v.x - m);
    v.y = __expf(v.y - m);
    v.z = __expf(v.z - m);
    v.w = __expf(v.w - m);
    float s = v.x + v.y + v.z + v.w;
#pragma unroll
    for (int o = 16; o; o >>= 1) s += __shfl_xor_sync(0xffffffffu, s, o);
    float inv = 1.f / s;
    __nv_bfloat162 p0 = __floats2bfloat162_rn(v.x * inv, v.y * inv);
    __nv_bfloat162 p1 = __floats2bfloat162_rn(v.z * inv, v.w * inv);
    uint2 u;
    u.x = *(unsigned*)&p0;
    u.y = *(unsigned*)&p1;
    ((uint2*)(g_attb + (((size_t)(b * 64 + h) * 64 + rr) << 7)))[lane] = u;
  }
}

// ---------------------------------------------------------------------------
// outH (wmma, 128 threads): per (b, w, c-tile 64 within [c_base, c_base+256)).
// ---------------------------------------------------------------------------
__global__ __launch_bounds__(128, 6) void out_h_wmma(int c_base) {
  const int ch0 = c_base + blockIdx.x * 64;
  const int w = blockIdx.y, b = blockIdx.z;
  __shared__ __align__(16) char smem[18432];
  bf16(*A)[72] = (bf16(*)[72])smem;
  bf16(*V)[72] = (bf16(*)[72])(smem + 9216);
  float(*C)[72] = (float(*)[72])smem;  // aliased
  const int tid = threadIdx.x;
  const int row = tid >> 1, cb = (tid & 1) * 32;

  {
    const bf16* asrc = g_attb + (((size_t)(b * 64 + row) * 64 + w) << 7) + cb;
#pragma unroll
    for (int i = 0; i < 4; i++)
      *(uint4*)&A[row][cb + i * 8] = *(const uint4*)(asrc + i * 8);
  }
  {
    const bf16* vsrc = g_pv + ((size_t)b * NHW + row * 64 + w) * NC + ch0 + cb;
#pragma unroll
    for (int i = 0; i < 4; i++)
      *(uint4*)&V[row][cb + i * 8] = *(const uint4*)(vsrc + i * 8);
  }
  __syncthreads();

  const int wh = tid >> 5;
  wmma::fragment<wmma::accumulator, 16, 16, 16, float> acc[4];
#pragma unroll
  for (int j = 0; j < 4; j++) wmma::fill_fragment(acc[j], 0.0f);
#pragma unroll
  for (int kk = 0; kk < 64; kk += 16) {
    wmma::fragment<wmma::matrix_a, 16, 16, 16, bf16, wmma::row_major> af;
    wmma::load_matrix_sync(af, &A[wh * 16][kk], 72);
#pragma unroll
    for (int fn = 0; fn < 4; fn++) {
      wmma::fragment<wmma::matrix_b, 16, 16, 16, bf16, wmma::row_major> bfr;
      wmma::load_matrix_sync(bfr, &V[kk][fn * 16], 72);
      wmma::mma_sync(acc[fn], af, bfr, acc[fn]);
    }
  }
  __syncthreads();
#pragma unroll
  for (int fn = 0; fn < 4; fn++)
    wmma::store_matrix_sync(&C[wh * 16][fn * 16], acc[fn], 72,
                            wmma::mem_row_major);
  __syncthreads();

  __align__(16) bf16 ov[32];
#pragma unroll
  for (int i = 0; i < 32; i++) ov[i] = __float2bfloat16(C[row][cb + i]);
  bf16* dst = g_oH + ((size_t)b * NHW + row * 64 + w) * NC + ch0 + cb;
#pragma unroll
  for (int i = 0; i < 4; i++) *(uint4*)(dst + i * 8) = *(uint4*)(ov + i * 8);
}

// ---------------------------------------------------------------------------
// outW + full epilogue (128 threads): per (b, h, c-tile 64 within half).
// ---------------------------------------------------------------------------
__global__ __launch_bounds__(128, 6) void out_w_final(
    const float* __restrict__ vin, const float* __restrict__ gptr,
    float* __restrict__ out, int c_base) {
  const int ch0 = c_base + blockIdx.x * 64;
  const int h = blockIdx.y, b = blockIdx.z;
  __shared__ __align__(16) char smem[18432];
  bf16(*A)[72] = (bf16(*)[72])smem;
  bf16(*V)[72] = (bf16(*)[72])(smem + 9216);
  float(*C)[72] = (float(*)[72])smem;
  const int tid = threadIdx.x;
  const int row = tid >> 1, cb = (tid & 1) * 32;

  {
    const bf16* asrc =
        g_attb + (((size_t)(b * 64 + h) * 64 + row) << 7) + 64 + cb;
#pragma unroll
    for (int i = 0; i < 4; i++)
      *(uint4*)&A[row][cb + i * 8] = *(const uint4*)(asrc + i * 8);
  }
  {
    const bf16* vsrc = g_pv + ((size_t)b * NHW + h * 64 + row) * NC + ch0 + cb;
#pragma unroll
    for (int i = 0; i < 4; i++)
      *(uint4*)&V[row][cb + i * 8] = *(const uint4*)(vsrc + i * 8);
  }
  __syncthreads();

  const int wh = tid >> 5;
  wmma::fragment<wmma::accumulator, 16, 16, 16, float> acc[4];
#pragma unroll
  for (int j = 0; j < 4; j++) wmma::fill_fragment(acc[j], 0.0f);
#pragma unroll
  for (int kk = 0; kk < 64; kk += 16) {
    wmma::fragment<wmma::matrix_a, 16, 16, 16, bf16, wmma::row_major> af;
    wmma::load_matrix_sync(af, &A[wh * 16][kk], 72);
#pragma unroll
    for (int fn = 0; fn < 4; fn++) {
      wmma::fragment<wmma::matrix_b, 16, 16, 16, bf16, wmma::row_major> bfr;
      wmma::load_matrix_sync(bfr, &V[kk][fn * 16], 72);
      wmma::mma_sync(acc[fn], af, bfr, acc[fn]);
    }
  }
  __syncthreads();
#pragma unroll
  for (int fn = 0; fn < 4; fn++)
    wmma::store_matrix_sync(&C[wh * 16][fn * 16], acc[fn], 72,
                            wmma::mem_row_major);
  __syncthreads();

  {
    const bf16* ohp = g_oH + ((size_t)b * NHW + h * 64 + row) * NC + ch0 + cb;
#pragma unroll
    for (int j = 0; j < 4; j++) {
      uint4 u4 = *(const uint4*)(ohp + j * 8);
      const bf16* e = (const bf16*)&u4;
#pragma unroll
      for (int t = 0; t < 8; t++)
        C[row][cb + j * 8 + t] += __bfloat162float(e[t]);
    }
  }
  __syncthreads();

  const float gamma = gptr[0];
  const int c = tid >> 1, wb = (tid & 1) * 32;
  const size_t base = ((size_t)(b * NC + ch0 + c) * 64 + h) * 64 + wb;
#pragma unroll
  for (int i = 0; i < 32; i += 4) {
    float4 vv = *(const float4*)(vin + base + i);
    float4 r;
    r.x = gamma * C[wb + i + 0][c] + vv.x;
    r.y = gamma * C[wb + i + 1][c] + vv.y;
    r.z = gamma * C[wb + i + 2][c] + vv.z;
    r.w = gamma * C[wb + i + 3][c] + vv.w;
    *(float4*)(out + base + i) = r;
  }
}

// ---------------------------------------------------------------------------
extern "C" void kernel_launch(void* const* d_in, const int* in_sizes, int n_in,
                              void* d_out, int out_size) {
  const float* q  = (const float*)d_in[0];
  const float* k  = (const float*)d_in[1];
  const float* v  = (const float*)d_in[2];
  const float* Wq = (const float*)d_in[3];
  const float* bq = (const float*)d_in[4];
  const float* Wk = (const float*)d_in[5];
  const float* bk = (const float*)d_in[6];
  const float* Wv = (const float*)d_in[7];
  const float* bv = (const float*)d_in[8];
  const float* gm = (const float*)d_in[9];
  float* out = (float*)d_out;

  bf16 *pq_d, *pk_d, *pv_d;
  cudaGetSymbolAddress((void**)&pq_d, g_pq);
  cudaGetSymbolAddress((void**)&pk_d, g_pk);
  cudaGetSymbolAddress((void**)&pv_d, g_pv);

  // Fork: proj_k on s1, proj_v on s2, proj_q + logits chain on capture stream.
  cudaEventRecord(g_ss.e0, 0);
  cudaStreamWaitEvent(g_ss.s1, g_ss.e0, 0);
  cudaStreamWaitEvent(g_ss.s2, g_ss.e0, 0);

  proj_wmma<64, 64, 3, false><<<dim3(32, 1, 8), 256, 0, g_ss.s1>>>(Wk, bk, k, pk_d);
  cudaEventRecord(g_ss.ek, g_ss.s1);

  // proj_v: m-tile fastest so the 4 blocks sharing an X slice are adjacent.
  proj_wmma<128, 512, 2, true><<<dim3(4, 32, 8), 256, 0, g_ss.s2>>>(Wv, bv, v, pv_d);
  cudaEventRecord(g_ss.ev, g_ss.s2);

  proj_wmma<64, 64, 3, false><<<dim3(32, 1, 8), 256>>>(Wq, bq, q, pq_d);

  cudaStreamWaitEvent(0, g_ss.ek, 0);
  logits_h_wmma<<<dim3(64, 8), 256>>>();
  logits_w_fused<<<dim3(64, 8), 256>>>();
  cudaEventRecord(g_ss.ea, 0);

  // Out stage, pipelined by c-halves:
  //   main: out_h(c0) -> out_h(c1) -> out_w(c1)
  //   s2:   out_w(c0) (after out_h(c0) + attention), concurrent with out_h(c1)
  cudaStreamWaitEvent(0, g_ss.ev, 0);
  out_h_wmma<<<dim3(4, 64, 8), 128>>>(0);
  cudaEventRecord(g_ss.eh0, 0);
  out_h_wmma<<<dim3(4, 64, 8), 128>>>(256);

  cudaStreamWaitEvent(g_ss.s2, g_ss.ea, 0);
  cudaStreamWaitEvent(g_ss.s2, g_ss.eh0, 0);
  out_w_final<<<dim3(4, 64, 8), 128, 0, g_ss.s2>>>(v, gm, out, 0);
  cudaEventRecord(g_ss.ew0, g_ss.s2);

  out_w_final<<<dim3(4, 64, 8), 128>>>(v, gm, out, 256);
  cudaStreamWaitEvent(0, g_ss.ew0, 0);
}

// round 12
// speedup vs baseline: 1.0301x; 1.0301x over previous
#include <cuda_runtime.h>
#include <cuda_bf16.h>
#include <mma.h>
#include <math.h>

using namespace nvcuda;
typedef __nv_bfloat16 bf16;

#define NB 8
#define NC 512
#define NC8 64
#define NHW 4096

#define NEG_INF (__int_as_float(0xff800000))

// Scratch (__device__ globals; allocation-free rule)
__device__ bf16  g_pq[NB * NHW * NC8];    //  4.2 MB  [b][hw][c8]
__device__ bf16  g_pk[NB * NHW * NC8];    //  4.2 MB  [b][hw][c8]
__device__ bf16  g_pv[NB * NHW * NC];     // 33.5 MB  [b][hw][c]
__device__ bf16  g_xv[NB * NC * NHW];     // 33.5 MB  v input pre-converted bf16
__device__ float g_attH[NB * NHW * 64];   //  8.4 MB  eH logits fp32 (compact)
__device__ bf16  g_attb[NB * NHW * 128];  //  8.4 MB  softmaxed bf16
__device__ bf16  g_oH[NB * NHW * NC];     // 33.5 MB  outH, bf16, [b][hw][c]

// Streams/events created at program load (before harness mem checkpoints).
namespace {
struct StreamSet {
  cudaStream_t s1, s2;
  cudaEvent_t e0, ek, ev;
  StreamSet() {
    cudaStreamCreateWithFlags(&s1, cudaStreamNonBlocking);
    cudaStreamCreateWithFlags(&s2, cudaStreamNonBlocking);
    cudaEventCreateWithFlags(&e0, cudaEventDisableTiming);
    cudaEventCreateWithFlags(&ek, cudaEventDisableTiming);
    cudaEventCreateWithFlags(&ev, cudaEventDisableTiming);
  }
};
StreamSet g_ss;
}  // namespace

// Pack 8 fp32 (two float4) -> uint4 of bf16
static __device__ __forceinline__ uint4 pack8_bf16(const float4& a, const float4& b) {
  __nv_bfloat162 p0 = __floats2bfloat162_rn(a.x, a.y);
  __nv_bfloat162 p1 = __floats2bfloat162_rn(a.z, a.w);
  __nv_bfloat162 p2 = __floats2bfloat162_rn(b.x, b.y);
  __nv_bfloat162 p3 = __floats2bfloat162_rn(b.z, b.w);
  uint4 u;
  u.x = *(unsigned*)&p0;
  u.y = *(unsigned*)&p1;
  u.z = *(unsigned*)&p2;
  u.w = *(unsigned*)&p3;
  return u;
}

// ---------------------------------------------------------------------------
// Streaming fp32 -> bf16 conversion (v input), 8 elements/thread.
// ---------------------------------------------------------------------------
__global__ __launch_bounds__(256) void conv_bf16(const float* __restrict__ X) {
  const size_t i = ((size_t)blockIdx.x * 256 + threadIdx.x) * 8;
  float4 a = *(const float4*)(X + i);
  float4 b = *(const float4*)(X + i + 4);
  *(uint4*)(g_xv + i) = pack8_bf16(a, b);
}

// ---------------------------------------------------------------------------
// q/k projection GEMM (wmma bf16, reg-prefetch pipelined), fp32 inputs:
//   P[b][n][m] = sum_k W[m][k] * X[b][k][n] + bias[m]   (channels-last out)
// BM=64, BN=128, BK=32.
// ---------------------------------------------------------------------------
__global__ __launch_bounds__(256, 3) void proj_qk(
    const float* __restrict__ W, const float* __restrict__ bias,
    const float* __restrict__ X, bf16* __restrict__ P) {
  constexpr int BK = 32;
  __shared__ __align__(16) char smem[34816];
  bf16(*As)[40] = (bf16(*)[40])smem;                   // [64][40]
  bf16(*Bs)[136] = (bf16(*)[136])(smem + 64 * 40 * 2); // [32][136]
  float(*Cs)[136] = (float(*)[136])smem;               // [64][136] aliased

  const int b = blockIdx.z;
  const int n0 = blockIdx.x * 128;
  const int tid = threadIdx.x;
  const int wid = tid >> 5;
  const int wm = wid & 1;
  const int wn = wid >> 1;
  const float* Xb = X + (size_t)b * NC * NHW;

  wmma::fragment<wmma::accumulator, 16, 16, 16, float> acc[2][2];
#pragma unroll
  for (int i = 0; i < 2; i++)
#pragma unroll
    for (int j = 0; j < 2; j++) wmma::fill_fragment(acc[i][j], 0.0f);

  float4 aR[2], bR[2][2];
  {
    int row = tid >> 2, kb = (tid & 3) * 8;
    const float* p = W + (size_t)row * NC + kb;
    aR[0] = *(const float4*)p;
    aR[1] = *(const float4*)(p + 4);
  }
#pragma unroll
  for (int r = 0; r < 2; r++) {
    int i = tid + r * 256, kr = i >> 4, nb = (i & 15) * 8;
    const float* p = Xb + (size_t)kr * NHW + n0 + nb;
    bR[r][0] = *(const float4*)p;
    bR[r][1] = *(const float4*)(p + 4);
  }

  for (int k0 = 0; k0 < NC; k0 += BK) {
    __syncthreads();
    {
      int row = tid >> 2, kb = (tid & 3) * 8;
      *(uint4*)&As[row][kb] = pack8_bf16(aR[0], aR[1]);
    }
#pragma unroll
    for (int r = 0; r < 2; r++) {
      int i = tid + r * 256, kr = i >> 4, nb = (i & 15) * 8;
      *(uint4*)&Bs[kr][nb] = pack8_bf16(bR[r][0], bR[r][1]);
    }
    __syncthreads();
    if (k0 + BK < NC) {
      int row = tid >> 2, kb = (tid & 3) * 8;
      const float* p = W + (size_t)row * NC + k0 + BK + kb;
      aR[0] = *(const float4*)p;
      aR[1] = *(const float4*)(p + 4);
#pragma unroll
      for (int r = 0; r < 2; r++) {
        int i = tid + r * 256, kr = i >> 4, nb = (i & 15) * 8;
        const float* pB = Xb + (size_t)(k0 + BK + kr) * NHW + n0 + nb;
        bR[r][0] = *(const float4*)pB;
        bR[r][1] = *(const float4*)(pB + 4);
      }
    }
#pragma unroll
    for (int kk = 0; kk < BK; kk += 16) {
      wmma::fragment<wmma::matrix_a, 16, 16, 16, bf16, wmma::row_major> af[2];
      wmma::load_matrix_sync(af[0], &As[wm * 32][kk], 40);
      wmma::load_matrix_sync(af[1], &As[wm * 32 + 16][kk], 40);
#pragma unroll
      for (int fn = 0; fn < 2; fn++) {
        wmma::fragment<wmma::matrix_b, 16, 16, 16, bf16, wmma::row_major> bfr;
        wmma::load_matrix_sync(bfr, &Bs[kk][wn * 32 + fn * 16], 136);
        wmma::mma_sync(acc[0][fn], af[0], bfr, acc[0][fn]);
        wmma::mma_sync(acc[1][fn], af[1], bfr, acc[1][fn]);
      }
    }
  }

  __syncthreads();
#pragma unroll
  for (int fm = 0; fm < 2; fm++)
#pragma unroll
    for (int fn = 0; fn < 2; fn++)
      wmma::store_matrix_sync(&Cs[wm * 32 + fm * 16][wn * 32 + fn * 16],
                              acc[fm][fn], 136, wmma::mem_row_major);
  __syncthreads();
  const int n = tid >> 1, ml = (tid & 1) * 32;
  __align__(16) bf16 ov[32];
#pragma unroll
  for (int i = 0; i < 32; i++)
    ov[i] = __float2bfloat16(Cs[ml + i][n] + bias[ml + i]);
  bf16* dst = P + ((size_t)b * NHW + n0 + n) * NC8 + ml;
#pragma unroll
  for (int i = 0; i < 4; i++) *(uint4*)(dst + i * 8) = *(uint4*)(ov + i * 8);
}

// ---------------------------------------------------------------------------
// v projection GEMM reading PRE-CONVERTED bf16 X (g_xv): BM=128, BN=128, BK=32.
// B-tile smem fill is a pass-through uint4 copy (no cvt in hot loop).
// ---------------------------------------------------------------------------
__global__ __launch_bounds__(256, 2) void proj_v_bf16(
    const float* __restrict__ W, const float* __restrict__ bias,
    bf16* __restrict__ P) {
  constexpr int BK = 32;
  __shared__ __align__(16) char smem[34816];
  bf16(*As)[40] = (bf16(*)[40])smem;                     // [128][40] 10240 B
  bf16(*Bs)[136] = (bf16(*)[136])(smem + 10240);         // [32][136]  8704 B
  float(*Cs)[136] = (float(*)[136])smem;                 // [64][136] aliased

  const int b = blockIdx.z;
  const int n0 = blockIdx.x * 128;
  const int m0 = blockIdx.y * 128;
  const int tid = threadIdx.x;
  const int wid = tid >> 5;
  const int wm = wid & 3;   // 4 m-subtiles of 32
  const int wn = wid >> 2;  // 2 n-subtiles of 64
  const bf16* Xb = g_xv + (size_t)b * NC * NHW;

  wmma::fragment<wmma::accumulator, 16, 16, 16, float> acc[2][4];
#pragma unroll
  for (int i = 0; i < 2; i++)
#pragma unroll
    for (int j = 0; j < 4; j++) wmma::fill_fragment(acc[i][j], 0.0f);

  float4 aR[2][2];
  uint4 bR[2];
#pragma unroll
  for (int r = 0; r < 2; r++) {
    int i = tid + r * 256, row = i >> 2, kb = (i & 3) * 8;
    const float* p = W + (size_t)(m0 + row) * NC + kb;
    aR[r][0] = *(const float4*)p;
    aR[r][1] = *(const float4*)(p + 4);
  }
#pragma unroll
  for (int r = 0; r < 2; r++) {
    int i = tid + r * 256, kr = i >> 4, nb = (i & 15) * 8;
    bR[r] = *(const uint4*)(Xb + (size_t)kr * NHW + n0 + nb);
  }

  for (int k0 = 0; k0 < NC; k0 += BK) {
    __syncthreads();
#pragma unroll
    for (int r = 0; r < 2; r++) {
      int i = tid + r * 256, row = i >> 2, kb = (i & 3) * 8;
      *(uint4*)&As[row][kb] = pack8_bf16(aR[r][0], aR[r][1]);
    }
#pragma unroll
    for (int r = 0; r < 2; r++) {
      int i = tid + r * 256, kr = i >> 4, nb = (i & 15) * 8;
      *(uint4*)&Bs[kr][nb] = bR[r];
    }
    __syncthreads();
    if (k0 + BK < NC) {
#pragma unroll
      for (int r = 0; r < 2; r++) {
        int i = tid + r * 256, row = i >> 2, kb = (i & 3) * 8;
        const float* p = W + (size_t)(m0 + row) * NC + k0 + BK + kb;
        aR[r][0] = *(const float4*)p;
        aR[r][1] = *(const float4*)(p + 4);
      }
#pragma unroll
      for (int r = 0; r < 2; r++) {
        int i = tid + r * 256, kr = i >> 4, nb = (i & 15) * 8;
        bR[r] = *(const uint4*)(Xb + (size_t)(k0 + BK + kr) * NHW + n0 + nb);
      }
    }
#pragma unroll
    for (int kk = 0; kk < BK; kk += 16) {
      wmma::fragment<wmma::matrix_a, 16, 16, 16, bf16, wmma::row_major> af[2];
      wmma::load_matrix_sync(af[0], &As[wm * 32][kk], 40);
      wmma::load_matrix_sync(af[1], &As[wm * 32 + 16][kk], 40);
#pragma unroll
      for (int fn = 0; fn < 4; fn++) {
        wmma::fragment<wmma::matrix_b, 16, 16, 16, bf16, wmma::row_major> bfr;
        wmma::load_matrix_sync(bfr, &Bs[kk][wn * 64 + fn * 16], 136);
        wmma::mma_sync(acc[0][fn], af[0], bfr, acc[0][fn]);
        wmma::mma_sync(acc[1][fn], af[1], bfr, acc[1][fn]);
      }
    }
  }

  // epilogue: 2 halves of 64 m-rows staged through Cs
#pragma unroll
  for (int half = 0; half < 2; half++) {
    __syncthreads();
    if ((wm >> 1) == half) {
      int mloc = (wm & 1) * 32;
#pragma unroll
      for (int fm = 0; fm < 2; fm++)
#pragma unroll
        for (int fn = 0; fn < 4; fn++)
          wmma::store_matrix_sync(&Cs[mloc + fm * 16][wn * 64 + fn * 16],
                                  acc[fm][fn], 136, wmma::mem_row_major);
    }
    __syncthreads();
    const int n = tid >> 1, ml = (tid & 1) * 32;
    const int mg = m0 + half * 64 + ml;
    __align__(16) bf16 ov[32];
#pragma unroll
    for (int i = 0; i < 32; i++)
      ov[i] = __float2bfloat16(Cs[ml + i][n] + bias[mg + i]);
    bf16* dst = P + ((size_t)b * NHW + n0 + n) * NC + mg;
#pragma unroll
    for (int i = 0; i < 4; i++) *(uint4*)(dst + i * 8) = *(uint4*)(ov + i * 8);
  }
}

// ---------------------------------------------------------------------------
// eH logits (wmma): per (b, w). E[h][k] = sum_c Q[h][c]*K[k][c]; diag -inf.
// ---------------------------------------------------------------------------
__global__ __launch_bounds__(256) void logits_h_wmma() {
  const int w = blockIdx.x, b = blockIdx.y;
  __shared__ __align__(32) bf16 Qs[64][72];
  __shared__ __align__(32) bf16 Ks[64][72];
  __shared__ __align__(32) float Cs[64][68];
  const int tid = threadIdx.x;
  const int r = tid >> 2, cb = (tid & 3) * 16;

  const bf16* qsrc = g_pq + ((size_t)b * NHW + r * 64 + w) * NC8 + cb;
  const bf16* ksrc = g_pk + ((size_t)b * NHW + r * 64 + w) * NC8 + cb;
  *(uint4*)&Qs[r][cb] = *(const uint4*)qsrc;
  *(uint4*)&Qs[r][cb + 8] = *(const uint4*)(qsrc + 8);
  *(uint4*)&Ks[r][cb] = *(const uint4*)ksrc;
  *(uint4*)&Ks[r][cb + 8] = *(const uint4*)(ksrc + 8);
  __syncthreads();

  const int wid = tid >> 5;
  const int wm = wid & 3, wn = wid >> 2;
  wmma::fragment<wmma::accumulator, 16, 16, 16, float> acc[2];
  wmma::fill_fragment(acc[0], 0.0f);
  wmma::fill_fragment(acc[1], 0.0f);
#pragma unroll
  for (int kk = 0; kk < 64; kk += 16) {
    wmma::fragment<wmma::matrix_a, 16, 16, 16, bf16, wmma::row_major> af;
    wmma::load_matrix_sync(af, &Qs[wm * 16][kk], 72);
#pragma unroll
    for (int j = 0; j < 2; j++) {
      wmma::fragment<wmma::matrix_b, 16, 16, 16, bf16, wmma::col_major> bfr;
      wmma::load_matrix_sync(bfr, &Ks[wn * 32 + j * 16][kk], 72);
      wmma::mma_sync(acc[j], af, bfr, acc[j]);
    }
  }
  wmma::store_matrix_sync(&Cs[wm * 16][wn * 32], acc[0], 68, wmma::mem_row_major);
  wmma::store_matrix_sync(&Cs[wm * 16][wn * 32 + 16], acc[1], 68, wmma::mem_row_major);
  __syncthreads();

  const int h = tid >> 2, kb = (tid & 3) * 16;
  float* dst = g_attH + (((size_t)(b * 64 + h) * 64 + w) << 6) + kb;
#pragma unroll
  for (int i = 0; i < 16; i += 4) {
    float4 v;
    v.x = (h == kb + i + 0) ? NEG_INF : Cs[h][kb + i + 0];
    v.y = (h == kb + i + 1) ? NEG_INF : Cs[h][kb + i + 1];
    v.z = (h == kb + i + 2) ? NEG_INF : Cs[h][kb + i + 2];
    v.w = (h == kb + i + 3) ? NEG_INF : Cs[h][kb + i + 3];
    *(float4*)(dst + i) = v;
  }
}

// ---------------------------------------------------------------------------
// eW logits + fused softmax: per (b, h).
// ---------------------------------------------------------------------------
__global__ __launch_bounds__(256) void logits_w_fused() {
  const int h = blockIdx.x, b = blockIdx.y;
  __shared__ __align__(16) char smQK[18432];
  __shared__ __align__(16) float Es[64][68];
  bf16(*Qs)[72] = (bf16(*)[72])smQK;
  bf16(*Ks)[72] = (bf16(*)[72])(smQK + 9216);
  float(*Cs)[68] = (float(*)[68])smQK;  // aliased after MMA
  const int tid = threadIdx.x;
  const int r = tid >> 2, cb = (tid & 3) * 16;

  const bf16* qsrc = g_pq + ((size_t)b * NHW + h * 64 + r) * NC8 + cb;
  const bf16* ksrc = g_pk + ((size_t)b * NHW + h * 64 + r) * NC8 + cb;
  *(uint4*)&Qs[r][cb] = *(const uint4*)qsrc;
  *(uint4*)&Qs[r][cb + 8] = *(const uint4*)(qsrc + 8);
  *(uint4*)&Ks[r][cb] = *(const uint4*)ksrc;
  *(uint4*)&Ks[r][cb + 8] = *(const uint4*)(ksrc + 8);
  const float* esrc = g_attH + (((size_t)(b * 64 + h) * 64 + r) << 6) + cb;
#pragma unroll
  for (int i = 0; i < 16; i += 4)
    *(float4*)&Es[r][cb + i] = *(const float4*)(esrc + i);
  __syncthreads();

  const int wid = tid >> 5;
  const int wm = wid & 3, wn = wid >> 2;
  wmma::fragment<wmma::accumulator, 16, 16, 16, float> acc[2];
  wmma::fill_fragment(acc[0], 0.0f);
  wmma::fill_fragment(acc[1], 0.0f);
#pragma unroll
  for (int kk = 0; kk < 64; kk += 16) {
    wmma::fragment<wmma::matrix_a, 16, 16, 16, bf16, wmma::row_major> af;
    wmma::load_matrix_sync(af, &Qs[wm * 16][kk], 72);
#pragma unroll
    for (int j = 0; j < 2; j++) {
      wmma::fragment<wmma::matrix_b, 16, 16, 16, bf16, wmma::col_major> bfr;
      wmma::load_matrix_sync(bfr, &Ks[wn * 32 + j * 16][kk], 72);
      wmma::mma_sync(acc[j], af, bfr, acc[j]);
    }
  }
  __syncthreads();  // Qs/Ks reads done; safe to alias as Cs
  wmma::store_matrix_sync(&Cs[wm * 16][wn * 32], acc[0], 68, wmma::mem_row_major);
  wmma::store_matrix_sync(&Cs[wm * 16][wn * 32 + 16], acc[1], 68, wmma::mem_row_major);
  __syncthreads();

  const int lane = tid & 31;
  for (int rr = wid; rr < 64; rr += 8) {
    float4 v;
    if (lane < 16)
      v = *(const float4*)&Es[rr][lane * 4];
    else
      v = *(const float4*)&Cs[rr][(lane - 16) * 4];
    float m = fmaxf(fmaxf(v.x, v.y), fmaxf(v.z, v.w));
#pragma unroll
    for (int o = 16; o; o >>= 1) m = fmaxf(m, __shfl_xor_sync(0xffffffffu, m, o));
    v.x = __expf(v.x - m);
    v.y = __expf(v.y - m);
    v.z = __expf(v.z - m);
    v.w = __expf(v.w - m);
    float s = v.x + v.y + v.z + v.w;
#pragma unroll
    for (int o = 16; o; o >>= 1) s += __shfl_xor_sync(0xffffffffu, s, o);
    float inv = 1.f / s;
    __nv_bfloat162 p0 = __floats2bfloat162_rn(v.x * inv, v.y * inv);
    __nv_bfloat162 p1 = __floats2bfloat162_rn(v.z * inv, v.w * inv);
    uint2 u;
    u.x = *(unsigned*)&p0;
    u.y = *(unsigned*)&p1;
    ((uint2*)(g_attb + (((size_t)(b * 64 + h) * 64 + rr) << 7)))[lane] = u;
  }
}

// ---------------------------------------------------------------------------
// outH (wmma, 128 threads): per (b, w, c-tile 64).
// ---------------------------------------------------------------------------
__global__ __launch_bounds__(128, 6) void out_h_wmma() {
  const int ch0 = blockIdx.x * 64;
  const int w = blockIdx.y, b = blockIdx.z;
  __shared__ __align__(16) char smem[18432];
  bf16(*A)[72] = (bf16(*)[72])smem;
  bf16(*V)[72] = (bf16(*)[72])(smem + 9216);
  float(*C)[72] = (float(*)[72])smem;  // aliased
  const int tid = threadIdx.x;
  const int row = tid >> 1, cb = (tid & 1) * 32;

  {
    const bf16* asrc = g_attb + (((size_t)(b * 64 + row) * 64 + w) << 7) + cb;
#pragma unroll
    for (int i = 0; i < 4; i++)
      *(uint4*)&A[row][cb + i * 8] = *(const uint4*)(asrc + i * 8);
  }
  {
    const bf16* vsrc = g_pv + ((size_t)b * NHW + row * 64 + w) * NC + ch0 + cb;
#pragma unroll
    for (int i = 0; i < 4; i++)
      *(uint4*)&V[row][cb + i * 8] = *(const uint4*)(vsrc + i * 8);
  }
  __syncthreads();

  const int wh = tid >> 5;
  wmma::fragment<wmma::accumulator, 16, 16, 16, float> acc[4];
#pragma unroll
  for (int j = 0; j < 4; j++) wmma::fill_fragment(acc[j], 0.0f);
#pragma unroll
  for (int kk = 0; kk < 64; kk += 16) {
    wmma::fragment<wmma::matrix_a, 16, 16, 16, bf16, wmma::row_major> af;
    wmma::load_matrix_sync(af, &A[wh * 16][kk], 72);
#pragma unroll
    for (int fn = 0; fn < 4; fn++) {
      wmma::fragment<wmma::matrix_b, 16, 16, 16, bf16, wmma::row_major> bfr;
      wmma::load_matrix_sync(bfr, &V[kk][fn * 16], 72);
      wmma::mma_sync(acc[fn], af, bfr, acc[fn]);
    }
  }
  __syncthreads();
#pragma unroll
  for (int fn = 0; fn < 4; fn++)
    wmma::store_matrix_sync(&C[wh * 16][fn * 16], acc[fn], 72,
                            wmma::mem_row_major);
  __syncthreads();

  __align__(16) bf16 ov[32];
#pragma unroll
  for (int i = 0; i < 32; i++) ov[i] = __float2bfloat16(C[row][cb + i]);
  bf16* dst = g_oH + ((size_t)b * NHW + row * 64 + w) * NC + ch0 + cb;
#pragma unroll
  for (int i = 0; i < 4; i++) *(uint4*)(dst + i * 8) = *(uint4*)(ov + i * 8);
}

// ---------------------------------------------------------------------------
// outW + full epilogue (128 threads): per (b, h, c-tile 64).
// ---------------------------------------------------------------------------
__global__ __launch_bounds__(128, 6) void out_w_final(
    const float* __restrict__ vin, const float* __restrict__ gptr,
    float* __restrict__ out) {
  const int ch0 = blockIdx.x * 64;
  const int h = blockIdx.y, b = blockIdx.z;
  __shared__ __align__(16) char smem[18432];
  bf16(*A)[72] = (bf16(*)[72])smem;
  bf16(*V)[72] = (bf16(*)[72])(smem + 9216);
  float(*C)[72] = (float(*)[72])smem;
  const int tid = threadIdx.x;
  const int row = tid >> 1, cb = (tid & 1) * 32;

  {
    const bf16* asrc =
        g_attb + (((size_t)(b * 64 + h) * 64 + row) << 7) + 64 + cb;
#pragma unroll
    for (int i = 0; i < 4; i++)
      *(uint4*)&A[row][cb + i * 8] = *(const uint4*)(asrc + i * 8);
  }
  {
    const bf16* vsrc = g_pv + ((size_t)b * NHW + h * 64 + row) * NC + ch0 + cb;
#pragma unroll
    for (int i = 0; i < 4; i++)
      *(uint4*)&V[row][cb + i * 8] = *(const uint4*)(vsrc + i * 8);
  }
  __syncthreads();

  const int wh = tid >> 5;
  wmma::fragment<wmma::accumulator, 16, 16, 16, float> acc[4];
#pragma unroll
  for (int j = 0; j < 4; j++) wmma::fill_fragment(acc[j], 0.0f);
#pragma unroll
  for (int kk = 0; kk < 64; kk += 16) {
    wmma::fragment<wmma::matrix_a, 16, 16, 16, bf16, wmma::row_major> af;
    wmma::load_matrix_sync(af, &A[wh * 16][kk], 72);
#pragma unroll
    for (int fn = 0; fn < 4; fn++) {
      wmma::fragment<wmma::matrix_b, 16, 16, 16, bf16, wmma::row_major> bfr;
      wmma::load_matrix_sync(bfr, &V[kk][fn * 16], 72);
      wmma::mma_sync(acc[fn], af, bfr, acc[fn]);
    }
  }
  __syncthreads();
#pragma unroll
  for (int fn = 0; fn < 4; fn++)
    wmma::store_matrix_sync(&C[wh * 16][fn * 16], acc[fn], 72,
                            wmma::mem_row_major);
  __syncthreads();

  {
    const bf16* ohp = g_oH + ((size_t)b * NHW + h * 64 + row) * NC + ch0 + cb;
#pragma unroll
    for (int j = 0; j < 4; j++) {
      uint4 u4 = *(const uint4*)(ohp + j * 8);
      const bf16* e = (const bf16*)&u4;
#pragma unroll
      for (int t = 0; t < 8; t++)
        C[row][cb + j * 8 + t] += __bfloat162float(e[t]);
    }
  }
  __syncthreads();

  const float gamma = gptr[0];
  const int c = tid >> 1, wb = (tid & 1) * 32;
  const size_t base = ((size_t)(b * NC + ch0 + c) * 64 + h) * 64 + wb;
#pragma unroll
  for (int i = 0; i < 32; i += 4) {
    float4 vv = *(const float4*)(vin + base + i);
    float4 r;
    r.x = gamma * C[wb + i + 0][c] + vv.x;
    r.y = gamma * C[wb + i + 1][c] + vv.y;
    r.z = gamma * C[wb + i + 2][c] + vv.z;
    r.w = gamma * C[wb + i + 3][c] + vv.w;
    *(float4*)(out + base + i) = r;
  }
}

// ---------------------------------------------------------------------------
extern "C" void kernel_launch(void* const* d_in, const int* in_sizes, int n_in,
                              void* d_out, int out_size) {
  const float* q  = (const float*)d_in[0];
  const float* k  = (const float*)d_in[1];
  const float* v  = (const float*)d_in[2];
  const float* Wq = (const float*)d_in[3];
  const float* bq = (const float*)d_in[4];
  const float* Wk = (const float*)d_in[5];
  const float* bk = (const float*)d_in[6];
  const float* Wv = (const float*)d_in[7];
  const float* bv = (const float*)d_in[8];
  const float* gm = (const float*)d_in[9];
  float* out = (float*)d_out;

  bf16 *pq_d, *pk_d, *pv_d;
  cudaGetSymbolAddress((void**)&pq_d, g_pq);
  cudaGetSymbolAddress((void**)&pk_d, g_pk);
  cudaGetSymbolAddress((void**)&pv_d, g_pv);

  // Fork: proj_k on s1, v chain (convert -> proj) on s2, q + logits on main.
  cudaEventRecord(g_ss.e0, 0);
  cudaStreamWaitEvent(g_ss.s1, g_ss.e0, 0);
  cudaStreamWaitEvent(g_ss.s2, g_ss.e0, 0);

  proj_qk<<<dim3(32, 1, 8), 256, 0, g_ss.s1>>>(Wk, bk, k, pk_d);
  cudaEventRecord(g_ss.ek, g_ss.s1);

  conv_bf16<<<8192, 256, 0, g_ss.s2>>>(v);
  proj_v_bf16<<<dim3(32, 4, 8), 256, 0, g_ss.s2>>>(Wv, bv, pv_d);
  cudaEventRecord(g_ss.ev, g_ss.s2);

  proj_qk<<<dim3(32, 1, 8), 256>>>(Wq, bq, q, pq_d);

  cudaStreamWaitEvent(0, g_ss.ek, 0);
  logits_h_wmma<<<dim3(64, 8), 256>>>();
  logits_w_fused<<<dim3(64, 8), 256>>>();

  cudaStreamWaitEvent(0, g_ss.ev, 0);
  out_h_wmma<<<dim3(8, 64, 8), 128>>>();
  out_w_final<<<dim3(8, 64, 8), 128>>>(v, gm, out);
}

// round 13
// speedup vs baseline: 1.0302x; 1.0001x over previous
#include <cuda_runtime.h>
#include <cuda_bf16.h>
#include <mma.h>
#include <math.h>

using namespace nvcuda;
typedef __nv_bfloat16 bf16;

#define NB 8
#define NC 512
#define NC8 64
#define NHW 4096

#define NEG_INF (__int_as_float(0xff800000))

// Scratch (__device__ globals; allocation-free rule)
__device__ bf16  g_pq[NB * NHW * NC8];    //  4.2 MB  [b][hw][c8]
__device__ bf16  g_pk[NB * NHW * NC8];    //  4.2 MB  [b][hw][c8]
__device__ bf16  g_pv[NB * NHW * NC];     // 33.5 MB  [b][hw][c]
__device__ bf16  g_xv[NB * NC * NHW];     // 33.5 MB  v input pre-converted bf16
__device__ float g_attH[NB * NHW * 64];   //  8.4 MB  eH logits fp32 (compact)
__device__ bf16  g_attb[NB * NHW * 128];  //  8.4 MB  softmaxed bf16
__device__ bf16  g_oH[NB * NHW * NC];     // 33.5 MB  outH, bf16, [b][hw][c]

// Streams/events created at program load (before harness mem checkpoints).
namespace {
struct StreamSet {
  cudaStream_t s1, s2;
  cudaEvent_t e0, ek, ev;
  StreamSet() {
    cudaStreamCreateWithFlags(&s1, cudaStreamNonBlocking);
    cudaStreamCreateWithFlags(&s2, cudaStreamNonBlocking);
    cudaEventCreateWithFlags(&e0, cudaEventDisableTiming);
    cudaEventCreateWithFlags(&ek, cudaEventDisableTiming);
    cudaEventCreateWithFlags(&ev, cudaEventDisableTiming);
  }
};
StreamSet g_ss;
}  // namespace

// cp.async helpers
static __device__ __forceinline__ void cp_async16(void* smem_dst, const void* gmem_src) {
  unsigned s = (unsigned)__cvta_generic_to_shared(smem_dst);
  asm volatile("cp.async.cg.shared.global [%0], [%1], 16;\n" ::"r"(s), "l"(gmem_src));
}
static __device__ __forceinline__ void cp_commit() {
  asm volatile("cp.async.commit_group;\n");
}
template <int N>
static __device__ __forceinline__ void cp_wait() {
  asm volatile("cp.async.wait_group %0;\n" ::"n"(N));
}

// Pack 8 fp32 (two float4) -> uint4 of bf16
static __device__ __forceinline__ uint4 pack8_bf16(const float4& a, const float4& b) {
  __nv_bfloat162 p0 = __floats2bfloat162_rn(a.x, a.y);
  __nv_bfloat162 p1 = __floats2bfloat162_rn(a.z, a.w);
  __nv_bfloat162 p2 = __floats2bfloat162_rn(b.x, b.y);
  __nv_bfloat162 p3 = __floats2bfloat162_rn(b.z, b.w);
  uint4 u;
  u.x = *(unsigned*)&p0;
  u.y = *(unsigned*)&p1;
  u.z = *(unsigned*)&p2;
  u.w = *(unsigned*)&p3;
  return u;
}

// ---------------------------------------------------------------------------
// Streaming fp32 -> bf16 conversion (v input), 8 elements/thread.
// ---------------------------------------------------------------------------
__global__ __launch_bounds__(256) void conv_bf16(const float* __restrict__ X) {
  const size_t i = ((size_t)blockIdx.x * 256 + threadIdx.x) * 8;
  float4 a = *(const float4*)(X + i);
  float4 b = *(const float4*)(X + i + 4);
  *(uint4*)(g_xv + i) = pack8_bf16(a, b);
}

// ---------------------------------------------------------------------------
// q/k projection GEMM (wmma bf16, reg-prefetch pipelined), fp32 inputs.
// BM=64, BN=128, BK=32.
// ---------------------------------------------------------------------------
__global__ __launch_bounds__(256, 3) void proj_qk(
    const float* __restrict__ W, const float* __restrict__ bias,
    const float* __restrict__ X, bf16* __restrict__ P) {
  constexpr int BK = 32;
  __shared__ __align__(16) char smem[34816];
  bf16(*As)[40] = (bf16(*)[40])smem;
  bf16(*Bs)[136] = (bf16(*)[136])(smem + 64 * 40 * 2);
  float(*Cs)[136] = (float(*)[136])smem;

  const int b = blockIdx.z;
  const int n0 = blockIdx.x * 128;
  const int tid = threadIdx.x;
  const int wid = tid >> 5;
  const int wm = wid & 1;
  const int wn = wid >> 1;
  const float* Xb = X + (size_t)b * NC * NHW;

  wmma::fragment<wmma::accumulator, 16, 16, 16, float> acc[2][2];
#pragma unroll
  for (int i = 0; i < 2; i++)
#pragma unroll
    for (int j = 0; j < 2; j++) wmma::fill_fragment(acc[i][j], 0.0f);

  float4 aR[2], bR[2][2];
  {
    int row = tid >> 2, kb = (tid & 3) * 8;
    const float* p = W + (size_t)row * NC + kb;
    aR[0] = *(const float4*)p;
    aR[1] = *(const float4*)(p + 4);
  }
#pragma unroll
  for (int r = 0; r < 2; r++) {
    int i = tid + r * 256, kr = i >> 4, nb = (i & 15) * 8;
    const float* p = Xb + (size_t)kr * NHW + n0 + nb;
    bR[r][0] = *(const float4*)p;
    bR[r][1] = *(const float4*)(p + 4);
  }

  for (int k0 = 0; k0 < NC; k0 += BK) {
    __syncthreads();
    {
      int row = tid >> 2, kb = (tid & 3) * 8;
      *(uint4*)&As[row][kb] = pack8_bf16(aR[0], aR[1]);
    }
#pragma unroll
    for (int r = 0; r < 2; r++) {
      int i = tid + r * 256, kr = i >> 4, nb = (i & 15) * 8;
      *(uint4*)&Bs[kr][nb] = pack8_bf16(bR[r][0], bR[r][1]);
    }
    __syncthreads();
    if (k0 + BK < NC) {
      int row = tid >> 2, kb = (tid & 3) * 8;
      const float* p = W + (size_t)row * NC + k0 + BK + kb;
      aR[0] = *(const float4*)p;
      aR[1] = *(const float4*)(p + 4);
#pragma unroll
      for (int r = 0; r < 2; r++) {
        int i = tid + r * 256, kr = i >> 4, nb = (i & 15) * 8;
        const float* pB = Xb + (size_t)(k0 + BK + kr) * NHW + n0 + nb;
        bR[r][0] = *(const float4*)pB;
        bR[r][1] = *(const float4*)(pB + 4);
      }
    }
#pragma unroll
    for (int kk = 0; kk < BK; kk += 16) {
      wmma::fragment<wmma::matrix_a, 16, 16, 16, bf16, wmma::row_major> af[2];
      wmma::load_matrix_sync(af[0], &As[wm * 32][kk], 40);
      wmma::load_matrix_sync(af[1], &As[wm * 32 + 16][kk], 40);
#pragma unroll
      for (int fn = 0; fn < 2; fn++) {
        wmma::fragment<wmma::matrix_b, 16, 16, 16, bf16, wmma::row_major> bfr;
        wmma::load_matrix_sync(bfr, &Bs[kk][wn * 32 + fn * 16], 136);
        wmma::mma_sync(acc[0][fn], af[0], bfr, acc[0][fn]);
        wmma::mma_sync(acc[1][fn], af[1], bfr, acc[1][fn]);
      }
    }
  }

  __syncthreads();
#pragma unroll
  for (int fm = 0; fm < 2; fm++)
#pragma unroll
    for (int fn = 0; fn < 2; fn++)
      wmma::store_matrix_sync(&Cs[wm * 32 + fm * 16][wn * 32 + fn * 16],
                              acc[fm][fn], 136, wmma::mem_row_major);
  __syncthreads();
  const int n = tid >> 1, ml = (tid & 1) * 32;
  __align__(16) bf16 ov[32];
#pragma unroll
  for (int i = 0; i < 32; i++)
    ov[i] = __float2bfloat16(Cs[ml + i][n] + bias[ml + i]);
  bf16* dst = P + ((size_t)b * NHW + n0 + n) * NC8 + ml;
#pragma unroll
  for (int i = 0; i < 4; i++) *(uint4*)(dst + i * 8) = *(uint4*)(ov + i * 8);
}

// ---------------------------------------------------------------------------
// v projection GEMM reading PRE-CONVERTED bf16 X (g_xv): BM=128, BN=128, BK=32.
// ---------------------------------------------------------------------------
__global__ __launch_bounds__(256, 2) void proj_v_bf16(
    const float* __restrict__ W, const float* __restrict__ bias,
    bf16* __restrict__ P) {
  constexpr int BK = 32;
  __shared__ __align__(16) char smem[34816];
  bf16(*As)[40] = (bf16(*)[40])smem;
  bf16(*Bs)[136] = (bf16(*)[136])(smem + 10240);
  float(*Cs)[136] = (float(*)[136])smem;

  const int b = blockIdx.z;
  const int n0 = blockIdx.x * 128;
  const int m0 = blockIdx.y * 128;
  const int tid = threadIdx.x;
  const int wid = tid >> 5;
  const int wm = wid & 3;
  const int wn = wid >> 2;
  const bf16* Xb = g_xv + (size_t)b * NC * NHW;

  wmma::fragment<wmma::accumulator, 16, 16, 16, float> acc[2][4];
#pragma unroll
  for (int i = 0; i < 2; i++)
#pragma unroll
    for (int j = 0; j < 4; j++) wmma::fill_fragment(acc[i][j], 0.0f);

  float4 aR[2][2];
  uint4 bR[2];
#pragma unroll
  for (int r = 0; r < 2; r++) {
    int i = tid + r * 256, row = i >> 2, kb = (i & 3) * 8;
    const float* p = W + (size_t)(m0 + row) * NC + kb;
    aR[r][0] = *(const float4*)p;
    aR[r][1] = *(const float4*)(p + 4);
  }
#pragma unroll
  for (int r = 0; r < 2; r++) {
    int i = tid + r * 256, kr = i >> 4, nb = (i & 15) * 8;
    bR[r] = *(const uint4*)(Xb + (size_t)kr * NHW + n0 + nb);
  }

  for (int k0 = 0; k0 < NC; k0 += BK) {
    __syncthreads();
#pragma unroll
    for (int r = 0; r < 2; r++) {
      int i = tid + r * 256, row = i >> 2, kb = (i & 3) * 8;
      *(uint4*)&As[row][kb] = pack8_bf16(aR[r][0], aR[r][1]);
    }
#pragma unroll
    for (int r = 0; r < 2; r++) {
      int i = tid + r * 256, kr = i >> 4, nb = (i & 15) * 8;
      *(uint4*)&Bs[kr][nb] = bR[r];
    }
    __syncthreads();
    if (k0 + BK < NC) {
#pragma unroll
      for (int r = 0; r < 2; r++) {
        int i = tid + r * 256, row = i >> 2, kb = (i & 3) * 8;
        const float* p = W + (size_t)(m0 + row) * NC + k0 + BK + kb;
        aR[r][0] = *(const float4*)p;
        aR[r][1] = *(const float4*)(p + 4);
      }
#pragma unroll
      for (int r = 0; r < 2; r++) {
        int i = tid + r * 256, kr = i >> 4, nb = (i & 15) * 8;
        bR[r] = *(const uint4*)(Xb + (size_t)(k0 + BK + kr) * NHW + n0 + nb);
      }
    }
#pragma unroll
    for (int kk = 0; kk < BK; kk += 16) {
      wmma::fragment<wmma::matrix_a, 16, 16, 16, bf16, wmma::row_major> af[2];
      wmma::load_matrix_sync(af[0], &As[wm * 32][kk], 40);
      wmma::load_matrix_sync(af[1], &As[wm * 32 + 16][kk], 40);
#pragma unroll
      for (int fn = 0; fn < 4; fn++) {
        wmma::fragment<wmma::matrix_b, 16, 16, 16, bf16, wmma::row_major> bfr;
        wmma::load_matrix_sync(bfr, &Bs[kk][wn * 64 + fn * 16], 136);
        wmma::mma_sync(acc[0][fn], af[0], bfr, acc[0][fn]);
        wmma::mma_sync(acc[1][fn], af[1], bfr, acc[1][fn]);
      }
    }
  }

#pragma unroll
  for (int half = 0; half < 2; half++) {
    __syncthreads();
    if ((wm >> 1) == half) {
      int mloc = (wm & 1) * 32;
#pragma unroll
      for (int fm = 0; fm < 2; fm++)
#pragma unroll
        for (int fn = 0; fn < 4; fn++)
          wmma::store_matrix_sync(&Cs[mloc + fm * 16][wn * 64 + fn * 16],
                                  acc[fm][fn], 136, wmma::mem_row_major);
    }
    __syncthreads();
    const int n = tid >> 1, ml = (tid & 1) * 32;
    const int mg = m0 + half * 64 + ml;
    __align__(16) bf16 ov[32];
#pragma unroll
    for (int i = 0; i < 32; i++)
      ov[i] = __float2bfloat16(Cs[ml + i][n] + bias[mg + i]);
    bf16* dst = P + ((size_t)b * NHW + n0 + n) * NC + mg;
#pragma unroll
    for (int i = 0; i < 4; i++) *(uint4*)(dst + i * 8) = *(uint4*)(ov + i * 8);
  }
}

// ---------------------------------------------------------------------------
// eH logits (wmma): per (b, w). E[h][k] = sum_c Q[h][c]*K[k][c]; diag -inf.
// ---------------------------------------------------------------------------
__global__ __launch_bounds__(256) void logits_h_wmma() {
  const int w = blockIdx.x, b = blockIdx.y;
  __shared__ __align__(32) bf16 Qs[64][72];
  __shared__ __align__(32) bf16 Ks[64][72];
  __shared__ __align__(32) float Cs[64][68];
  const int tid = threadIdx.x;
  const int r = tid >> 2, cb = (tid & 3) * 16;

  const bf16* qsrc = g_pq + ((size_t)b * NHW + r * 64 + w) * NC8 + cb;
  const bf16* ksrc = g_pk + ((size_t)b * NHW + r * 64 + w) * NC8 + cb;
  *(uint4*)&Qs[r][cb] = *(const uint4*)qsrc;
  *(uint4*)&Qs[r][cb + 8] = *(const uint4*)(qsrc + 8);
  *(uint4*)&Ks[r][cb] = *(const uint4*)ksrc;
  *(uint4*)&Ks[r][cb + 8] = *(const uint4*)(ksrc + 8);
  __syncthreads();

  const int wid = tid >> 5;
  const int wm = wid & 3, wn = wid >> 2;
  wmma::fragment<wmma::accumulator, 16, 16, 16, float> acc[2];
  wmma::fill_fragment(acc[0], 0.0f);
  wmma::fill_fragment(acc[1], 0.0f);
#pragma unroll
  for (int kk = 0; kk < 64; kk += 16) {
    wmma::fragment<wmma::matrix_a, 16, 16, 16, bf16, wmma::row_major> af;
    wmma::load_matrix_sync(af, &Qs[wm * 16][kk], 72);
#pragma unroll
    for (int j = 0; j < 2; j++) {
      wmma::fragment<wmma::matrix_b, 16, 16, 16, bf16, wmma::col_major> bfr;
      wmma::load_matrix_sync(bfr, &Ks[wn * 32 + j * 16][kk], 72);
      wmma::mma_sync(acc[j], af, bfr, acc[j]);
    }
  }
  wmma::store_matrix_sync(&Cs[wm * 16][wn * 32], acc[0], 68, wmma::mem_row_major);
  wmma::store_matrix_sync(&Cs[wm * 16][wn * 32 + 16], acc[1], 68, wmma::mem_row_major);
  __syncthreads();

  const int h = tid >> 2, kb = (tid & 3) * 16;
  float* dst = g_attH + (((size_t)(b * 64 + h) * 64 + w) << 6) + kb;
#pragma unroll
  for (int i = 0; i < 16; i += 4) {
    float4 v;
    v.x = (h == kb + i + 0) ? NEG_INF : Cs[h][kb + i + 0];
    v.y = (h == kb + i + 1) ? NEG_INF : Cs[h][kb + i + 1];
    v.z = (h == kb + i + 2) ? NEG_INF : Cs[h][kb + i + 2];
    v.w = (h == kb + i + 3) ? NEG_INF : Cs[h][kb + i + 3];
    *(float4*)(dst + i) = v;
  }
}

// ---------------------------------------------------------------------------
// eW logits + fused softmax: per (b, h).
// ---------------------------------------------------------------------------
__global__ __launch_bounds__(256) void logits_w_fused() {
  const int h = blockIdx.x, b = blockIdx.y;
  __shared__ __align__(16) char smQK[18432];
  __shared__ __align__(16) float Es[64][68];
  bf16(*Qs)[72] = (bf16(*)[72])smQK;
  bf16(*Ks)[72] = (bf16(*)[72])(smQK + 9216);
  float(*Cs)[68] = (float(*)[68])smQK;  // aliased after MMA
  const int tid = threadIdx.x;
  const int r = tid >> 2, cb = (tid & 3) * 16;

  const bf16* qsrc = g_pq + ((size_t)b * NHW + h * 64 + r) * NC8 + cb;
  const bf16* ksrc = g_pk + ((size_t)b * NHW + h * 64 + r) * NC8 + cb;
  *(uint4*)&Qs[r][cb] = *(const uint4*)qsrc;
  *(uint4*)&Qs[r][cb + 8] = *(const uint4*)(qsrc + 8);
  *(uint4*)&Ks[r][cb] = *(const uint4*)ksrc;
  *(uint4*)&Ks[r][cb + 8] = *(const uint4*)(ksrc + 8);
  const float* esrc = g_attH + (((size_t)(b * 64 + h) * 64 + r) << 6) + cb;
#pragma unroll
  for (int i = 0; i < 16; i += 4)
    *(float4*)&Es[r][cb + i] = *(const float4*)(esrc + i);
  __syncthreads();

  const int wid = tid >> 5;
  const int wm = wid & 3, wn = wid >> 2;
  wmma::fragment<wmma::accumulator, 16, 16, 16, float> acc[2];
  wmma::fill_fragment(acc[0], 0.0f);
  wmma::fill_fragment(acc[1], 0.0f);
#pragma unroll
  for (int kk = 0; kk < 64; kk += 16) {
    wmma::fragment<wmma::matrix_a, 16, 16, 16, bf16, wmma::row_major> af;
    wmma::load_matrix_sync(af, &Qs[wm * 16][kk], 72);
#pragma unroll
    for (int j = 0; j < 2; j++) {
      wmma::fragment<wmma::matrix_b, 16, 16, 16, bf16, wmma::col_major> bfr;
      wmma::load_matrix_sync(bfr, &Ks[wn * 32 + j * 16][kk], 72);
      wmma::mma_sync(acc[j], af, bfr, acc[j]);
    }
  }
  __syncthreads();  // Qs/Ks reads done; safe to alias as Cs
  wmma::store_matrix_sync(&Cs[wm * 16][wn * 32], acc[0], 68, wmma::mem_row_major);
  wmma::store_matrix_sync(&Cs[wm * 16][wn * 32 + 16], acc[1], 68, wmma::mem_row_major);
  __syncthreads();

  const int lane = tid & 31;
  for (int rr = wid; rr < 64; rr += 8) {
    float4 v;
    if (lane < 16)
      v = *(const float4*)&Es[rr][lane * 4];
    else
      v = *(const float4*)&Cs[rr][(lane - 16) * 4];
    float m = fmaxf(fmaxf(v.x, v.y), fmaxf(v.z, v.w));
#pragma unroll
    for (int o = 16; o; o >>= 1) m = fmaxf(m, __shfl_xor_sync(0xffffffffu, m, o));
    v.x = __expf(v.x - m);
    v.y = __expf(v.y - m);
    v.z = __expf(v.z - m);
    v.w = __expf(v.w - m);
    float s = v.x + v.y + v.z + v.w;
#pragma unroll
    for (int o = 16; o; o >>= 1) s += __shfl_xor_sync(0xffffffffu, s, o);
    float inv = 1.f / s;
    __nv_bfloat162 p0 = __floats2bfloat162_rn(v.x * inv, v.y * inv);
    __nv_bfloat162 p1 = __floats2bfloat162_rn(v.z * inv, v.w * inv);
    uint2 u;
    u.x = *(unsigned*)&p0;
    u.y = *(unsigned*)&p1;
    ((uint2*)(g_attb + (((size_t)(b * 64 + h) * 64 + rr) << 7)))[lane] = u;
  }
}

// ---------------------------------------------------------------------------
// outH (wmma, 256 threads, c-tile 128, cp.async loads): per (b, w, c-tile).
// O[h][c] = sum_k aH[h][k]*pv[b][k*64+w][c]; bf16 to g_oH.
// ---------------------------------------------------------------------------
__global__ __launch_bounds__(256) void out_h_wmma() {
  const int ch0 = blockIdx.x * 128;
  const int w = blockIdx.y, b = blockIdx.z;
  __shared__ __align__(16) char smem[34816];
  bf16(*A)[72] = (bf16(*)[72])smem;                 // [64][72]
  bf16(*V)[136] = (bf16(*)[136])(smem + 9216);      // [64][136]
  float(*C)[136] = (float(*)[136])smem;             // aliased
  const int tid = threadIdx.x;

  // cp.async tile loads: A = 512 16B-chunks (2/thread), V = 1024 (4/thread)
#pragma unroll
  for (int r = 0; r < 2; r++) {
    int c = tid + r * 256, h = c >> 3, kb = (c & 7) * 8;
    cp_async16(&A[h][kb],
               g_attb + (((size_t)(b * 64 + h) * 64 + w) << 7) + kb);
  }
#pragma unroll
  for (int r = 0; r < 4; r++) {
    int c = tid + r * 256, k = c >> 4, cb = (c & 15) * 8;
    cp_async16(&V[k][cb],
               g_pv + ((size_t)b * NHW + k * 64 + w) * NC + ch0 + cb);
  }
  cp_commit();
  cp_wait<0>();
  __syncthreads();

  const int wid = tid >> 5;
  const int wh = wid & 3, wc = wid >> 2;
  wmma::fragment<wmma::accumulator, 16, 16, 16, float> acc[4];
#pragma unroll
  for (int j = 0; j < 4; j++) wmma::fill_fragment(acc[j], 0.0f);
#pragma unroll
  for (int kk = 0; kk < 64; kk += 16) {
    wmma::fragment<wmma::matrix_a, 16, 16, 16, bf16, wmma::row_major> af;
    wmma::load_matrix_sync(af, &A[wh * 16][kk], 72);
#pragma unroll
    for (int fn = 0; fn < 4; fn++) {
      wmma::fragment<wmma::matrix_b, 16, 16, 16, bf16, wmma::row_major> bfr;
      wmma::load_matrix_sync(bfr, &V[kk][wc * 64 + fn * 16], 136);
      wmma::mma_sync(acc[fn], af, bfr, acc[fn]);
    }
  }
  __syncthreads();  // all MMA reads of A/V done before aliasing as C
#pragma unroll
  for (int fn = 0; fn < 4; fn++)
    wmma::store_matrix_sync(&C[wh * 16][wc * 64 + fn * 16], acc[fn], 136,
                            wmma::mem_row_major);
  __syncthreads();

  const int h = tid >> 2, cb = (tid & 3) * 32;
  __align__(16) bf16 ov[32];
#pragma unroll
  for (int i = 0; i < 32; i++) ov[i] = __float2bfloat16(C[h][cb + i]);
  bf16* dst = g_oH + ((size_t)b * NHW + h * 64 + w) * NC + ch0 + cb;
#pragma unroll
  for (int i = 0; i < 4; i++) *(uint4*)(dst + i * 8) = *(uint4*)(ov + i * 8);
}

// ---------------------------------------------------------------------------
// outW + full epilogue (256 threads, c-tile 128, cp.async loads): per (b, h, ct).
// ---------------------------------------------------------------------------
__global__ __launch_bounds__(256) void out_w_final(
    const float* __restrict__ vin, const float* __restrict__ gptr,
    float* __restrict__ out) {
  const int ch0 = blockIdx.x * 128;
  const int h = blockIdx.y, b = blockIdx.z;
  __shared__ __align__(16) char smem[34816];
  bf16(*A)[72] = (bf16(*)[72])smem;
  bf16(*V)[136] = (bf16(*)[136])(smem + 9216);
  float(*C)[136] = (float(*)[136])smem;
  const int tid = threadIdx.x;

#pragma unroll
  for (int r = 0; r < 2; r++) {
    int c = tid + r * 256, w = c >> 3, kb = (c & 7) * 8;
    cp_async16(&A[w][kb],
               g_attb + (((size_t)(b * 64 + h) * 64 + w) << 7) + 64 + kb);
  }
#pragma unroll
  for (int r = 0; r < 4; r++) {
    int c = tid + r * 256, k = c >> 4, cb = (c & 15) * 8;
    cp_async16(&V[k][cb],
               g_pv + ((size_t)b * NHW + h * 64 + k) * NC + ch0 + cb);
  }
  cp_commit();
  cp_wait<0>();
  __syncthreads();

  const int wid = tid >> 5;
  const int ww = wid & 3, wc = wid >> 2;
  wmma::fragment<wmma::accumulator, 16, 16, 16, float> acc[4];
#pragma unroll
  for (int j = 0; j < 4; j++) wmma::fill_fragment(acc[j], 0.0f);
#pragma unroll
  for (int kk = 0; kk < 64; kk += 16) {
    wmma::fragment<wmma::matrix_a, 16, 16, 16, bf16, wmma::row_major> af;
    wmma::load_matrix_sync(af, &A[ww * 16][kk], 72);
#pragma unroll
    for (int fn = 0; fn < 4; fn++) {
      wmma::fragment<wmma::matrix_b, 16, 16, 16, bf16, wmma::row_major> bfr;
      wmma::load_matrix_sync(bfr, &V[kk][wc * 64 + fn * 16], 136);
      wmma::mma_sync(acc[fn], af, bfr, acc[fn]);
    }
  }
  __syncthreads();
#pragma unroll
  for (int fn = 0; fn < 4; fn++)
    wmma::store_matrix_sync(&C[ww * 16][wc * 64 + fn * 16], acc[fn], 136,
                            wmma::mem_row_major);
  __syncthreads();

  // add outH (bf16, coalesced rows of g_oH in [w][c] layout)
  {
    const int w = tid >> 2, cb = (tid & 3) * 32;
    const bf16* ohp = g_oH + ((size_t)b * NHW + h * 64 + w) * NC + ch0 + cb;
#pragma unroll
    for (int j = 0; j < 4; j++) {
      uint4 u4 = *(const uint4*)(ohp + j * 8);
      const bf16* e = (const bf16*)&u4;
#pragma unroll
      for (int t = 0; t < 8; t++)
        C[w][cb + j * 8 + t] += __bfloat162float(e[t]);
    }
  }
  __syncthreads();

  // final transposed write: out[b][ch0+c][h][w] = gamma*C[w][c] + v
  const float gamma = gptr[0];
  const int c = tid >> 1, wb = (tid & 1) * 32;
  const size_t base = ((size_t)(b * NC + ch0 + c) * 64 + h) * 64 + wb;
#pragma unroll
  for (int i = 0; i < 32; i += 4) {
    float4 vv = *(const float4*)(vin + base + i);
    float4 r;
    r.x = gamma * C[wb + i + 0][c] + vv.x;
    r.y = gamma * C[wb + i + 1][c] + vv.y;
    r.z = gamma * C[wb + i + 2][c] + vv.z;
    r.w = gamma * C[wb + i + 3][c] + vv.w;
    *(float4*)(out + base + i) = r;
  }
}

// ---------------------------------------------------------------------------
extern "C" void kernel_launch(void* const* d_in, const int* in_sizes, int n_in,
                              void* d_out, int out_size) {
  const float* q  = (const float*)d_in[0];
  const float* k  = (const float*)d_in[1];
  const float* v  = (const float*)d_in[2];
  const float* Wq = (const float*)d_in[3];
  const float* bq = (const float*)d_in[4];
  const float* Wk = (const float*)d_in[5];
  const float* bk = (const float*)d_in[6];
  const float* Wv = (const float*)d_in[7];
  const float* bv = (const float*)d_in[8];
  const float* gm = (const float*)d_in[9];
  float* out = (float*)d_out;

  bf16 *pq_d, *pk_d, *pv_d;
  cudaGetSymbolAddress((void**)&pq_d, g_pq);
  cudaGetSymbolAddress((void**)&pk_d, g_pk);
  cudaGetSymbolAddress((void**)&pv_d, g_pv);

  // Fork: proj_k on s1, v chain (convert -> proj) on s2, q + logits on main.
  cudaEventRecord(g_ss.e0, 0);
  cudaStreamWaitEvent(g_ss.s1, g_ss.e0, 0);
  cudaStreamWaitEvent(g_ss.s2, g_ss.e0, 0);

  proj_qk<<<dim3(32, 1, 8), 256, 0, g_ss.s1>>>(Wk, bk, k, pk_d);
  cudaEventRecord(g_ss.ek, g_ss.s1);

  conv_bf16<<<8192, 256, 0, g_ss.s2>>>(v);
  proj_v_bf16<<<dim3(32, 4, 8), 256, 0, g_ss.s2>>>(Wv, bv, pv_d);
  cudaEventRecord(g_ss.ev, g_ss.s2);

  proj_qk<<<dim3(32, 1, 8), 256>>>(Wq, bq, q, pq_d);

  cudaStreamWaitEvent(0, g_ss.ek, 0);
  logits_h_wmma<<<dim3(64, 8), 256>>>();
  logits_w_fused<<<dim3(64, 8), 256>>>();

  cudaStreamWaitEvent(0, g_ss.ev, 0);
  out_h_wmma<<<dim3(4, 64, 8), 256>>>();
  out_w_final<<<dim3(4, 64, 8), 256>>>(v, gm, out);
}

// round 14
// speedup vs baseline: 1.0380x; 1.0076x over previous
#include <cuda_runtime.h>
#include <cuda_bf16.h>
#include <mma.h>
#include <math.h>

using namespace nvcuda;
typedef __nv_bfloat16 bf16;

#define NB 8
#define NC 512
#define NC8 64
#define NHW 4096

#define NEG_INF (__int_as_float(0xff800000))

// Scratch (__device__ globals; allocation-free rule)
__device__ bf16  g_pq[NB * NHW * NC8];    //  4.2 MB  [b][hw][c8]
__device__ bf16  g_pk[NB * NHW * NC8];    //  4.2 MB  [b][hw][c8]
__device__ bf16  g_pv[NB * NHW * NC];     // 33.5 MB  [b][hw][c]
__device__ bf16  g_xv[NB * NC * NHW];     // 33.5 MB  v input pre-converted bf16
__device__ float g_attH[NB * NHW * 64];   //  8.4 MB  eH logits fp32 (compact)
__device__ bf16  g_attb[NB * NHW * 128];  //  8.4 MB  softmaxed bf16
__device__ bf16  g_oH[NB * NHW * NC];     // 33.5 MB  outH, bf16, [b][hw][c]

// Streams/events created at program load (before harness mem checkpoints).
namespace {
struct StreamSet {
  cudaStream_t s1, s2;
  cudaEvent_t e0, ek, ev;
  StreamSet() {
    cudaStreamCreateWithFlags(&s1, cudaStreamNonBlocking);
    cudaStreamCreateWithFlags(&s2, cudaStreamNonBlocking);
    cudaEventCreateWithFlags(&e0, cudaEventDisableTiming);
    cudaEventCreateWithFlags(&ek, cudaEventDisableTiming);
    cudaEventCreateWithFlags(&ev, cudaEventDisableTiming);
  }
};
StreamSet g_ss;
}  // namespace

// cp.async helpers
static __device__ __forceinline__ void cp_async16(void* smem_dst, const void* gmem_src) {
  unsigned s = (unsigned)__cvta_generic_to_shared(smem_dst);
  asm volatile("cp.async.cg.shared.global [%0], [%1], 16;\n" ::"r"(s), "l"(gmem_src));
}
static __device__ __forceinline__ void cp_commit() {
  asm volatile("cp.async.commit_group;\n");
}
template <int N>
static __device__ __forceinline__ void cp_wait() {
  asm volatile("cp.async.wait_group %0;\n" ::"n"(N));
}

// Pack 8 fp32 (two float4) -> uint4 of bf16
static __device__ __forceinline__ uint4 pack8_bf16(const float4& a, const float4& b) {
  __nv_bfloat162 p0 = __floats2bfloat162_rn(a.x, a.y);
  __nv_bfloat162 p1 = __floats2bfloat162_rn(a.z, a.w);
  __nv_bfloat162 p2 = __floats2bfloat162_rn(b.x, b.y);
  __nv_bfloat162 p3 = __floats2bfloat162_rn(b.z, b.w);
  uint4 u;
  u.x = *(unsigned*)&p0;
  u.y = *(unsigned*)&p1;
  u.z = *(unsigned*)&p2;
  u.w = *(unsigned*)&p3;
  return u;
}

// ---------------------------------------------------------------------------
// Streaming fp32 -> bf16 conversion (v input), 8 elements/thread.
// ---------------------------------------------------------------------------
__global__ __launch_bounds__(256) void conv_bf16(const float* __restrict__ X) {
  const size_t i = ((size_t)blockIdx.x * 256 + threadIdx.x) * 8;
  float4 a = *(const float4*)(X + i);
  float4 b = *(const float4*)(X + i + 4);
  *(uint4*)(g_xv + i) = pack8_bf16(a, b);
}

// ---------------------------------------------------------------------------
// q/k projection GEMM (wmma bf16, reg-prefetch pipelined), fp32 inputs.
// BM=64, BN=128, BK=32.
// ---------------------------------------------------------------------------
__global__ __launch_bounds__(256, 3) void proj_qk(
    const float* __restrict__ W, const float* __restrict__ bias,
    const float* __restrict__ X, bf16* __restrict__ P) {
  constexpr int BK = 32;
  __shared__ __align__(16) char smem[34816];
  bf16(*As)[40] = (bf16(*)[40])smem;
  bf16(*Bs)[136] = (bf16(*)[136])(smem + 64 * 40 * 2);
  float(*Cs)[136] = (float(*)[136])smem;

  const int b = blockIdx.z;
  const int n0 = blockIdx.x * 128;
  const int tid = threadIdx.x;
  const int wid = tid >> 5;
  const int wm = wid & 1;
  const int wn = wid >> 1;
  const float* Xb = X + (size_t)b * NC * NHW;

  wmma::fragment<wmma::accumulator, 16, 16, 16, float> acc[2][2];
#pragma unroll
  for (int i = 0; i < 2; i++)
#pragma unroll
    for (int j = 0; j < 2; j++) wmma::fill_fragment(acc[i][j], 0.0f);

  float4 aR[2], bR[2][2];
  {
    int row = tid >> 2, kb = (tid & 3) * 8;
    const float* p = W + (size_t)row * NC + kb;
    aR[0] = *(const float4*)p;
    aR[1] = *(const float4*)(p + 4);
  }
#pragma unroll
  for (int r = 0; r < 2; r++) {
    int i = tid + r * 256, kr = i >> 4, nb = (i & 15) * 8;
    const float* p = Xb + (size_t)kr * NHW + n0 + nb;
    bR[r][0] = *(const float4*)p;
    bR[r][1] = *(const float4*)(p + 4);
  }

  for (int k0 = 0; k0 < NC; k0 += BK) {
    __syncthreads();
    {
      int row = tid >> 2, kb = (tid & 3) * 8;
      *(uint4*)&As[row][kb] = pack8_bf16(aR[0], aR[1]);
    }
#pragma unroll
    for (int r = 0; r < 2; r++) {
      int i = tid + r * 256, kr = i >> 4, nb = (i & 15) * 8;
      *(uint4*)&Bs[kr][nb] = pack8_bf16(bR[r][0], bR[r][1]);
    }
    __syncthreads();
    if (k0 + BK < NC) {
      int row = tid >> 2, kb = (tid & 3) * 8;
      const float* p = W + (size_t)row * NC + k0 + BK + kb;
      aR[0] = *(const float4*)p;
      aR[1] = *(const float4*)(p + 4);
#pragma unroll
      for (int r = 0; r < 2; r++) {
        int i = tid + r * 256, kr = i >> 4, nb = (i & 15) * 8;
        const float* pB = Xb + (size_t)(k0 + BK + kr) * NHW + n0 + nb;
        bR[r][0] = *(const float4*)pB;
        bR[r][1] = *(const float4*)(pB + 4);
      }
    }
#pragma unroll
    for (int kk = 0; kk < BK; kk += 16) {
      wmma::fragment<wmma::matrix_a, 16, 16, 16, bf16, wmma::row_major> af[2];
      wmma::load_matrix_sync(af[0], &As[wm * 32][kk], 40);
      wmma::load_matrix_sync(af[1], &As[wm * 32 + 16][kk], 40);
#pragma unroll
      for (int fn = 0; fn < 2; fn++) {
        wmma::fragment<wmma::matrix_b, 16, 16, 16, bf16, wmma::row_major> bfr;
        wmma::load_matrix_sync(bfr, &Bs[kk][wn * 32 + fn * 16], 136);
        wmma::mma_sync(acc[0][fn], af[0], bfr, acc[0][fn]);
        wmma::mma_sync(acc[1][fn], af[1], bfr, acc[1][fn]);
      }
    }
  }

  __syncthreads();
#pragma unroll
  for (int fm = 0; fm < 2; fm++)
#pragma unroll
    for (int fn = 0; fn < 2; fn++)
      wmma::store_matrix_sync(&Cs[wm * 32 + fm * 16][wn * 32 + fn * 16],
                              acc[fm][fn], 136, wmma::mem_row_major);
  __syncthreads();
  const int n = tid >> 1, ml = (tid & 1) * 32;
  __align__(16) bf16 ov[32];
#pragma unroll
  for (int i = 0; i < 32; i++)
    ov[i] = __float2bfloat16(Cs[ml + i][n] + bias[ml + i]);
  bf16* dst = P + ((size_t)b * NHW + n0 + n) * NC8 + ml;
#pragma unroll
  for (int i = 0; i < 4; i++) *(uint4*)(dst + i * 8) = *(uint4*)(ov + i * 8);
}

// ---------------------------------------------------------------------------
// v projection GEMM, bf16 X (g_xv): BM=128, BN=128, BK=32.
// m-tile on blockIdx.x (fastest): 4 blocks sharing an X slice are
// launch-adjacent and co-resident -> 3 of 4 X reads hit L2.
// ---------------------------------------------------------------------------
__global__ __launch_bounds__(256, 2) void proj_v_bf16(
    const float* __restrict__ W, const float* __restrict__ bias,
    bf16* __restrict__ P) {
  constexpr int BK = 32;
  __shared__ __align__(16) char smem[34816];
  bf16(*As)[40] = (bf16(*)[40])smem;
  bf16(*Bs)[136] = (bf16(*)[136])(smem + 10240);
  float(*Cs)[136] = (float(*)[136])smem;

  const int b = blockIdx.z;
  const int m0 = blockIdx.x * 128;   // m-tile fastest (L2 reuse of X)
  const int n0 = blockIdx.y * 128;
  const int tid = threadIdx.x;
  const int wid = tid >> 5;
  const int wm = wid & 3;
  const int wn = wid >> 2;
  const bf16* Xb = g_xv + (size_t)b * NC * NHW;

  wmma::fragment<wmma::accumulator, 16, 16, 16, float> acc[2][4];
#pragma unroll
  for (int i = 0; i < 2; i++)
#pragma unroll
    for (int j = 0; j < 4; j++) wmma::fill_fragment(acc[i][j], 0.0f);

  float4 aR[2][2];
  uint4 bR[2];
#pragma unroll
  for (int r = 0; r < 2; r++) {
    int i = tid + r * 256, row = i >> 2, kb = (i & 3) * 8;
    const float* p = W + (size_t)(m0 + row) * NC + kb;
    aR[r][0] = *(const float4*)p;
    aR[r][1] = *(const float4*)(p + 4);
  }
#pragma unroll
  for (int r = 0; r < 2; r++) {
    int i = tid + r * 256, kr = i >> 4, nb = (i & 15) * 8;
    bR[r] = *(const uint4*)(Xb + (size_t)kr * NHW + n0 + nb);
  }

  for (int k0 = 0; k0 < NC; k0 += BK) {
    __syncthreads();
#pragma unroll
    for (int r = 0; r < 2; r++) {
      int i = tid + r * 256, row = i >> 2, kb = (i & 3) * 8;
      *(uint4*)&As[row][kb] = pack8_bf16(aR[r][0], aR[r][1]);
    }
#pragma unroll
    for (int r = 0; r < 2; r++) {
      int i = tid + r * 256, kr = i >> 4, nb = (i & 15) * 8;
      *(uint4*)&Bs[kr][nb] = bR[r];
    }
    __syncthreads();
    if (k0 + BK < NC) {
#pragma unroll
      for (int r = 0; r < 2; r++) {
        int i = tid + r * 256, row = i >> 2, kb = (i & 3) * 8;
        const float* p = W + (size_t)(m0 + row) * NC + k0 + BK + kb;
        aR[r][0] = *(const float4*)p;
        aR[r][1] = *(const float4*)(p + 4);
      }
#pragma unroll
      for (int r = 0; r < 2; r++) {
        int i = tid + r * 256, kr = i >> 4, nb = (i & 15) * 8;
        bR[r] = *(const uint4*)(Xb + (size_t)(k0 + BK + kr) * NHW + n0 + nb);
      }
    }
#pragma unroll
    for (int kk = 0; kk < BK; kk += 16) {
      wmma::fragment<wmma::matrix_a, 16, 16, 16, bf16, wmma::row_major> af[2];
      wmma::load_matrix_sync(af[0], &As[wm * 32][kk], 40);
      wmma::load_matrix_sync(af[1], &As[wm * 32 + 16][kk], 40);
#pragma unroll
      for (int fn = 0; fn < 4; fn++) {
        wmma::fragment<wmma::matrix_b, 16, 16, 16, bf16, wmma::row_major> bfr;
        wmma::load_matrix_sync(bfr, &Bs[kk][wn * 64 + fn * 16], 136);
        wmma::mma_sync(acc[0][fn], af[0], bfr, acc[0][fn]);
        wmma::mma_sync(acc[1][fn], af[1], bfr, acc[1][fn]);
      }
    }
  }

#pragma unroll
  for (int half = 0; half < 2; half++) {
    __syncthreads();
    if ((wm >> 1) == half) {
      int mloc = (wm & 1) * 32;
#pragma unroll
      for (int fm = 0; fm < 2; fm++)
#pragma unroll
        for (int fn = 0; fn < 4; fn++)
          wmma::store_matrix_sync(&Cs[mloc + fm * 16][wn * 64 + fn * 16],
                                  acc[fm][fn], 136, wmma::mem_row_major);
    }
    __syncthreads();
    const int n = tid >> 1, ml = (tid & 1) * 32;
    const int mg = m0 + half * 64 + ml;
    __align__(16) bf16 ov[32];
#pragma unroll
    for (int i = 0; i < 32; i++)
      ov[i] = __float2bfloat16(Cs[ml + i][n] + bias[mg + i]);
    bf16* dst = P + ((size_t)b * NHW + n0 + n) * NC + mg;
#pragma unroll
    for (int i = 0; i < 4; i++) *(uint4*)(dst + i * 8) = *(uint4*)(ov + i * 8);
  }
}

// ---------------------------------------------------------------------------
// eH logits (wmma): per (b, w). E[h][k] = sum_c Q[h][c]*K[k][c]; diag -inf.
// ---------------------------------------------------------------------------
__global__ __launch_bounds__(256) void logits_h_wmma() {
  const int w = blockIdx.x, b = blockIdx.y;
  __shared__ __align__(32) bf16 Qs[64][72];
  __shared__ __align__(32) bf16 Ks[64][72];
  __shared__ __align__(32) float Cs[64][68];
  const int tid = threadIdx.x;
  const int r = tid >> 2, cb = (tid & 3) * 16;

  const bf16* qsrc = g_pq + ((size_t)b * NHW + r * 64 + w) * NC8 + cb;
  const bf16* ksrc = g_pk + ((size_t)b * NHW + r * 64 + w) * NC8 + cb;
  *(uint4*)&Qs[r][cb] = *(const uint4*)qsrc;
  *(uint4*)&Qs[r][cb + 8] = *(const uint4*)(qsrc + 8);
  *(uint4*)&Ks[r][cb] = *(const uint4*)ksrc;
  *(uint4*)&Ks[r][cb + 8] = *(const uint4*)(ksrc + 8);
  __syncthreads();

  const int wid = tid >> 5;
  const int wm = wid & 3, wn = wid >> 2;
  wmma::fragment<wmma::accumulator, 16, 16, 16, float> acc[2];
  wmma::fill_fragment(acc[0], 0.0f);
  wmma::fill_fragment(acc[1], 0.0f);
#pragma unroll
  for (int kk = 0; kk < 64; kk += 16) {
    wmma::fragment<wmma::matrix_a, 16, 16, 16, bf16, wmma::row_major> af;
    wmma::load_matrix_sync(af, &Qs[wm * 16][kk], 72);
#pragma unroll
    for (int j = 0; j < 2; j++) {
      wmma::fragment<wmma::matrix_b, 16, 16, 16, bf16, wmma::col_major> bfr;
      wmma::load_matrix_sync(bfr, &Ks[wn * 32 + j * 16][kk], 72);
      wmma::mma_sync(acc[j], af, bfr, acc[j]);
    }
  }
  wmma::store_matrix_sync(&Cs[wm * 16][wn * 32], acc[0], 68, wmma::mem_row_major);
  wmma::store_matrix_sync(&Cs[wm * 16][wn * 32 + 16], acc[1], 68, wmma::mem_row_major);
  __syncthreads();

  const int h = tid >> 2, kb = (tid & 3) * 16;
  float* dst = g_attH + (((size_t)(b * 64 + h) * 64 + w) << 6) + kb;
#pragma unroll
  for (int i = 0; i < 16; i += 4) {
    float4 v;
    v.x = (h == kb + i + 0) ? NEG_INF : Cs[h][kb + i + 0];
    v.y = (h == kb + i + 1) ? NEG_INF : Cs[h][kb + i + 1];
    v.z = (h == kb + i + 2) ? NEG_INF : Cs[h][kb + i + 2];
    v.w = (h == kb + i + 3) ? NEG_INF : Cs[h][kb + i + 3];
    *(float4*)(dst + i) = v;
  }
}

// ---------------------------------------------------------------------------
// eW logits + fused softmax: per (b, h).
// ---------------------------------------------------------------------------
__global__ __launch_bounds__(256) void logits_w_fused() {
  const int h = blockIdx.x, b = blockIdx.y;
  __shared__ __align__(16) char smQK[18432];
  __shared__ __align__(16) float Es[64][68];
  bf16(*Qs)[72] = (bf16(*)[72])smQK;
  bf16(*Ks)[72] = (bf16(*)[72])(smQK + 9216);
  float(*Cs)[68] = (float(*)[68])smQK;  // aliased after MMA
  const int tid = threadIdx.x;
  const int r = tid >> 2, cb = (tid & 3) * 16;

  const bf16* qsrc = g_pq + ((size_t)b * NHW + h * 64 + r) * NC8 + cb;
  const bf16* ksrc = g_pk + ((size_t)b * NHW + h * 64 + r) * NC8 + cb;
  *(uint4*)&Qs[r][cb] = *(const uint4*)qsrc;
  *(uint4*)&Qs[r][cb + 8] = *(const uint4*)(qsrc + 8);
  *(uint4*)&Ks[r][cb] = *(const uint4*)ksrc;
  *(uint4*)&Ks[r][cb + 8] = *(const uint4*)(ksrc + 8);
  const float* esrc = g_attH + (((size_t)(b * 64 + h) * 64 + r) << 6) + cb;
#pragma unroll
  for (int i = 0; i < 16; i += 4)
    *(float4*)&Es[r][cb + i] = *(const float4*)(esrc + i);
  __syncthreads();

  const int wid = tid >> 5;
  const int wm = wid & 3, wn = wid >> 2;
  wmma::fragment<wmma::accumulator, 16, 16, 16, float> acc[2];
  wmma::fill_fragment(acc[0], 0.0f);
  wmma::fill_fragment(acc[1], 0.0f);
#pragma unroll
  for (int kk = 0; kk < 64; kk += 16) {
    wmma::fragment<wmma::matrix_a, 16, 16, 16, bf16, wmma::row_major> af;
    wmma::load_matrix_sync(af, &Qs[wm * 16][kk], 72);
#pragma unroll
    for (int j = 0; j < 2; j++) {
      wmma::fragment<wmma::matrix_b, 16, 16, 16, bf16, wmma::col_major> bfr;
      wmma::load_matrix_sync(bfr, &Ks[wn * 32 + j * 16][kk], 72);
      wmma::mma_sync(acc[j], af, bfr, acc[j]);
    }
  }
  __syncthreads();  // Qs/Ks reads done; safe to alias as Cs
  wmma::store_matrix_sync(&Cs[wm * 16][wn * 32], acc[0], 68, wmma::mem_row_major);
  wmma::store_matrix_sync(&Cs[wm * 16][wn * 32 + 16], acc[1], 68, wmma::mem_row_major);
  __syncthreads();

  const int lane = tid & 31;
  for (int rr = wid; rr < 64; rr += 8) {
    float4 v;
    if (lane < 16)
      v = *(const float4*)&Es[rr][lane * 4];
    else
      v = *(const float4*)&Cs[rr][(lane - 16) * 4];
    float m = fmaxf(fmaxf(v.x, v.y), fmaxf(v.z, v.w));
#pragma unroll
    for (int o = 16; o; o >>= 1) m = fmaxf(m, __shfl_xor_sync(0xffffffffu, m, o));
    v.x = __expf(v.x - m);
    v.y = __expf(v.y - m);
    v.z = __expf(v.z - m);
    v.w = __expf(v.w - m);
    float s = v.x + v.y + v.z + v.w;
#pragma unroll
    for (int o = 16; o; o >>= 1) s += __shfl_xor_sync(0xffffffffu, s, o);
    float inv = 1.f / s;
    __nv_bfloat162 p0 = __floats2bfloat162_rn(v.x * inv, v.y * inv);
    __nv_bfloat162 p1 = __floats2bfloat162_rn(v.z * inv, v.w * inv);
    uint2 u;
    u.x = *(unsigned*)&p0;
    u.y = *(unsigned*)&p1;
    ((uint2*)(g_attb + (((size_t)(b * 64 + h) * 64 + rr) << 7)))[lane] = u;
  }
}

// ---------------------------------------------------------------------------
// outH (wmma, 256 threads, c-tile 128, cp.async loads): per (b, w, c-tile).
// ---------------------------------------------------------------------------
__global__ __launch_bounds__(256) void out_h_wmma() {
  const int ch0 = blockIdx.x * 128;
  const int w = blockIdx.y, b = blockIdx.z;
  __shared__ __align__(16) char smem[34816];
  bf16(*A)[72] = (bf16(*)[72])smem;                 // [64][72]
  bf16(*V)[136] = (bf16(*)[136])(smem + 9216);      // [64][136]
  float(*C)[136] = (float(*)[136])smem;             // aliased
  const int tid = threadIdx.x;

#pragma unroll
  for (int r = 0; r < 2; r++) {
    int c = tid + r * 256, h = c >> 3, kb = (c & 7) * 8;
    cp_async16(&A[h][kb],
               g_attb + (((size_t)(b * 64 + h) * 64 + w) << 7) + kb);
  }
#pragma unroll
  for (int r = 0; r < 4; r++) {
    int c = tid + r * 256, k = c >> 4, cb = (c & 15) * 8;
    cp_async16(&V[k][cb],
               g_pv + ((size_t)b * NHW + k * 64 + w) * NC + ch0 + cb);
  }
  cp_commit();
  cp_wait<0>();
  __syncthreads();

  const int wid = tid >> 5;
  const int wh = wid & 3, wc = wid >> 2;
  wmma::fragment<wmma::accumulator, 16, 16, 16, float> acc[4];
#pragma unroll
  for (int j = 0; j < 4; j++) wmma::fill_fragment(acc[j], 0.0f);
#pragma unroll
  for (int kk = 0; kk < 64; kk += 16) {
    wmma::fragment<wmma::matrix_a, 16, 16, 16, bf16, wmma::row_major> af;
    wmma::load_matrix_sync(af, &A[wh * 16][kk], 72);
#pragma unroll
    for (int fn = 0; fn < 4; fn++) {
      wmma::fragment<wmma::matrix_b, 16, 16, 16, bf16, wmma::row_major> bfr;
      wmma::load_matrix_sync(bfr, &V[kk][wc * 64 + fn * 16], 136);
      wmma::mma_sync(acc[fn], af, bfr, acc[fn]);
    }
  }
  __syncthreads();
#pragma unroll
  for (int fn = 0; fn < 4; fn++)
    wmma::store_matrix_sync(&C[wh * 16][wc * 64 + fn * 16], acc[fn], 136,
                            wmma::mem_row_major);
  __syncthreads();

  const int h = tid >> 2, cb = (tid & 3) * 32;
  __align__(16) bf16 ov[32];
#pragma unroll
  for (int i = 0; i < 32; i++) ov[i] = __float2bfloat16(C[h][cb + i]);
  bf16* dst = g_oH + ((size_t)b * NHW + h * 64 + w) * NC + ch0 + cb;
#pragma unroll
  for (int i = 0; i < 4; i++) *(uint4*)(dst + i * 8) = *(uint4*)(ov + i * 8);
}

// ---------------------------------------------------------------------------
// outW + full epilogue (256 threads, c-tile 128, cp.async loads): per (b, h, ct).
// ---------------------------------------------------------------------------
__global__ __launch_bounds__(256) void out_w_final(
    const float* __restrict__ vin, const float* __restrict__ gptr,
    float* __restrict__ out) {
  const int ch0 = blockIdx.x * 128;
  const int h = blockIdx.y, b = blockIdx.z;
  __shared__ __align__(16) char smem[34816];
  bf16(*A)[72] = (bf16(*)[72])smem;
  bf16(*V)[136] = (bf16(*)[136])(smem + 9216);
  float(*C)[136] = (float(*)[136])smem;
  const int tid = threadIdx.x;

#pragma unroll
  for (int r = 0; r < 2; r++) {
    int c = tid + r * 256, w = c >> 3, kb = (c & 7) * 8;
    cp_async16(&A[w][kb],
               g_attb + (((size_t)(b * 64 + h) * 64 + w) << 7) + 64 + kb);
  }
#pragma unroll
  for (int r = 0; r < 4; r++) {
    int c = tid + r * 256, k = c >> 4, cb = (c & 15) * 8;
    cp_async16(&V[k][cb],
               g_pv + ((size_t)b * NHW + h * 64 + k) * NC + ch0 + cb);
  }
  cp_commit();
  cp_wait<0>();
  __syncthreads();

  const int wid = tid >> 5;
  const int ww = wid & 3, wc = wid >> 2;
  wmma::fragment<wmma::accumulator, 16, 16, 16, float> acc[4];
#pragma unroll
  for (int j = 0; j < 4; j++) wmma::fill_fragment(acc[j], 0.0f);
#pragma unroll
  for (int kk = 0; kk < 64; kk += 16) {
    wmma::fragment<wmma::matrix_a, 16, 16, 16, bf16, wmma::row_major> af;
    wmma::load_matrix_sync(af, &A[ww * 16][kk], 72);
#pragma unroll
    for (int fn = 0; fn < 4; fn++) {
      wmma::fragment<wmma::matrix_b, 16, 16, 16, bf16, wmma::row_major> bfr;
      wmma::load_matrix_sync(bfr, &V[kk][wc * 64 + fn * 16], 136);
      wmma::mma_sync(acc[fn], af, bfr, acc[fn]);
    }
  }
  __syncthreads();
#pragma unroll
  for (int fn = 0; fn < 4; fn++)
    wmma::store_matrix_sync(&C[ww * 16][wc * 64 + fn * 16], acc[fn], 136,
                            wmma::mem_row_major);
  __syncthreads();

  {
    const int w = tid >> 2, cb = (tid & 3) * 32;
    const bf16* ohp = g_oH + ((size_t)b * NHW + h * 64 + w) * NC + ch0 + cb;
#pragma unroll
    for (int j = 0; j < 4; j++) {
      uint4 u4 = *(const uint4*)(ohp + j * 8);
      const bf16* e = (const bf16*)&u4;
#pragma unroll
      for (int t = 0; t < 8; t++)
        C[w][cb + j * 8 + t] += __bfloat162float(e[t]);
    }
  }
  __syncthreads();

  const float gamma = gptr[0];
  const int c = tid >> 1, wb = (tid & 1) * 32;
  const size_t base = ((size_t)(b * NC + ch0 + c) * 64 + h) * 64 + wb;
#pragma unroll
  for (int i = 0; i < 32; i += 4) {
    float4 vv = *(const float4*)(vin + base + i);
    float4 r;
    r.x = gamma * C[wb + i + 0][c] + vv.x;
    r.y = gamma * C[wb + i + 1][c] + vv.y;
    r.z = gamma * C[wb + i + 2][c] + vv.z;
    r.w = gamma * C[wb + i + 3][c] + vv.w;
    *(float4*)(out + base + i) = r;
  }
}

// ---------------------------------------------------------------------------
extern "C" void kernel_launch(void* const* d_in, const int* in_sizes, int n_in,
                              void* d_out, int out_size) {
  const float* q  = (const float*)d_in[0];
  const float* k  = (const float*)d_in[1];
  const float* v  = (const float*)d_in[2];
  const float* Wq = (const float*)d_in[3];
  const float* bq = (const float*)d_in[4];
  const float* Wk = (const float*)d_in[5];
  const float* bk = (const float*)d_in[6];
  const float* Wv = (const float*)d_in[7];
  const float* bv = (const float*)d_in[8];
  const float* gm = (const float*)d_in[9];
  float* out = (float*)d_out;

  bf16 *pq_d, *pk_d, *pv_d;
  cudaGetSymbolAddress((void**)&pq_d, g_pq);
  cudaGetSymbolAddress((void**)&pk_d, g_pk);
  cudaGetSymbolAddress((void**)&pv_d, g_pv);

  // Fork: proj_k on s1, v chain (convert -> proj) on s2, q + logits on main.
  cudaEventRecord(g_ss.e0, 0);
  cudaStreamWaitEvent(g_ss.s1, g_ss.e0, 0);
  cudaStreamWaitEvent(g_ss.s2, g_ss.e0, 0);

  proj_qk<<<dim3(32, 1, 8), 256, 0, g_ss.s1>>>(Wk, bk, k, pk_d);
  cudaEventRecord(g_ss.ek, g_ss.s1);

  conv_bf16<<<8192, 256, 0, g_ss.s2>>>(v);
  // m-tile fastest: 4 adjacent blocks share X slice in L2
  proj_v_bf16<<<dim3(4, 32, 8), 256, 0, g_ss.s2>>>(Wv, bv, pv_d);
  cudaEventRecord(g_ss.ev, g_ss.s2);

  proj_qk<<<dim3(32, 1, 8), 256>>>(Wq, bq, q, pq_d);

  cudaStreamWaitEvent(0, g_ss.ek, 0);
  logits_h_wmma<<<dim3(64, 8), 256>>>();
  logits_w_fused<<<dim3(64, 8), 256>>>();

  cudaStreamWaitEvent(0, g_ss.ev, 0);
  out_h_wmma<<<dim3(4, 64, 8), 256>>>();
  out_w_final<<<dim3(4, 64, 8), 256>>>(v, gm, out);
}